// round 2
// baseline (speedup 1.0000x reference)
#include <cuda_runtime.h>
#include <math.h>

#define N_ENT  50000
#define NDIM   256
#define BSZ    1024
#define M_ROWS 2048
#define NPAD   50048   // 391 * 128, padded column count for the score matrix

typedef unsigned long long ull;

// ---------------- device scratch (allocation-free contract) ----------------
__device__ float  g_scale[3 * 256];
__device__ float  g_shift[3 * 256];
__device__ float  g_V[M_ROWS * NDIM];                 // head rows 0..1023, tail rows 1024..2047
__device__ float  g_S[(size_t)M_ROWS * NPAD];         // ~410 MB score scratch
__device__ double g_acc;

// ---------------- packed f32x2 helpers (FFMA2 path, 2x fp32 rate) ----------
__device__ __forceinline__ ull packdup(float a) {
    ull r; unsigned u = __float_as_uint(a);
    asm("mov.b64 %0, {%1, %2};" : "=l"(r) : "r"(u), "r"(u));
    return r;
}
__device__ __forceinline__ void fma2(ull& d, ull a, ull b) {
    asm("fma.rn.f32x2 %0, %1, %2, %0;" : "+l"(d) : "l"(a), "l"(b));
}

// ---------------- kernel 0: zero accumulator --------------------------------
__global__ void zero_acc_kernel() { g_acc = 0.0; }

// ---------------- kernel 1: batch-norm statistics ---------------------------
// grid (256 dims, 3 stats), block 256. s=0: ent_w[h], s=1: ent_w[t], s=2: rel_w[r]
__global__ void bn_stats_kernel(const int* __restrict__ facts,
                                const float* __restrict__ ent_w,
                                const float* __restrict__ rel_w,
                                const float* __restrict__ bg_e,
                                const float* __restrict__ bb_e,
                                const float* __restrict__ bg_r,
                                const float* __restrict__ bb_r) {
    int d = blockIdx.x, s = blockIdx.y, tid = threadIdx.x;
    const float* W = (s == 2) ? rel_w : ent_w;
    float sum = 0.f, sq = 0.f;
    for (int b = tid; b < BSZ; b += 256) {
        int idx = facts[b * 3 + s];
        float x = W[idx * NDIM + d];
        sum += x; sq += x * x;
    }
    __shared__ float s1[256], s2[256];
    s1[tid] = sum; s2[tid] = sq; __syncthreads();
    for (int o = 128; o > 0; o >>= 1) {
        if (tid < o) { s1[tid] += s1[tid + o]; s2[tid] += s2[tid + o]; }
        __syncthreads();
    }
    if (tid == 0) {
        float mean = s1[0] * (1.f / BSZ);
        float var  = s2[0] * (1.f / BSZ) - mean * mean;
        float gamma = (s == 2) ? bg_r[d] : bg_e[d];
        float beta  = (s == 2) ? bb_r[d] : bb_e[d];
        float sc = gamma * rsqrtf(var + 1e-5f);
        g_scale[s * 256 + d] = sc;
        g_shift[s * 256 + d] = beta - mean * sc;
    }
}

// ---------------- kernel 2: head/tail query vectors -------------------------
// grid 1024 (one per fact), block 256 (thread = k*64+l)
__global__ void build_vec_kernel(const int* __restrict__ facts,
                                 const int* __restrict__ arch,
                                 const float* __restrict__ ent_w,
                                 const float* __restrict__ rel_w) {
    int b = blockIdx.x, tid = threadIdx.x;
    __shared__ float hen[256], ten[256], ren[256], al[64];
    int h = facts[3 * b], t = facts[3 * b + 1], r = facts[3 * b + 2];
    hen[tid] = ent_w[h * NDIM + tid] * g_scale[tid]       + g_shift[tid];
    ten[tid] = ent_w[t * NDIM + tid] * g_scale[256 + tid] + g_shift[256 + tid];
    ren[tid] = rel_w[r * NDIM + tid] * g_scale[512 + tid] + g_shift[512 + tid];
    if (tid < 64) {
        int a = arch[tid];
        al[tid] = (a == 1) ? 1.f : ((a == 2) ? -1.f : 0.f);
    }
    __syncthreads();
    int k = tid >> 6, l = tid & 63;
    float hv = 0.f, tv = 0.f;
#pragma unroll
    for (int i = 0; i < 4; i++) {
        float rv = ren[i * 64 + l];
#pragma unroll
        for (int j = 0; j < 4; j++) {
            hv += al[i * 16 + j * 4 + k] * rv * ten[j * 64 + l];   // alpha[i][j][k]
            tv += al[i * 16 + k * 4 + j] * rv * hen[j * 64 + l];   // alpha[i][k][j]
        }
    }
    g_V[b * NDIM + tid]              = hv;
    g_V[(BSZ + b) * NDIM + tid]      = tv;
}

// ---------------- kernel 3: S = V (2048x256) @ ent_w^T (256x50000) ----------
// BM=128, BN=128, BK=16, 256 threads, 8x8 per thread, FFMA2 inner product.
#define BMG 128
#define BNG 128
#define BKG 16

__global__ __launch_bounds__(256, 2) void gemm_kernel(const float* __restrict__ E) {
    __shared__ float Vs[BKG][BMG];
    __shared__ float Es[BKG][BNG];
    int tid = threadIdx.x;
    int n0 = blockIdx.x * BNG, m0 = blockIdx.y * BMG;
    int tx = tid & 15, ty = tid >> 4;

    ull acc[8][4];
#pragma unroll
    for (int i = 0; i < 8; i++)
#pragma unroll
        for (int p = 0; p < 4; p++) acc[i][p] = 0ull;   // bit pattern (0.f, 0.f)

    for (int kt = 0; kt < NDIM; kt += BKG) {
        __syncthreads();
#pragma unroll
        for (int j = 0; j < 2; j++) {
            int f  = tid + j * 256;      // 0..511
            int r  = f >> 2;             // tile row 0..127
            int kq = f & 3;              // which float4 along k
            float4 v = *(const float4*)&g_V[(size_t)(m0 + r) * NDIM + kt + kq * 4];
            Vs[kq * 4 + 0][r] = v.x; Vs[kq * 4 + 1][r] = v.y;
            Vs[kq * 4 + 2][r] = v.z; Vs[kq * 4 + 3][r] = v.w;
            int gr = n0 + r; if (gr >= N_ENT) gr = 0;   // clamp for tail tile
            float4 e = *(const float4*)&E[(size_t)gr * NDIM + kt + kq * 4];
            Es[kq * 4 + 0][r] = e.x; Es[kq * 4 + 1][r] = e.y;
            Es[kq * 4 + 2][r] = e.z; Es[kq * 4 + 3][r] = e.w;
        }
        __syncthreads();
#pragma unroll
        for (int k = 0; k < BKG; k++) {
            float4 va = *(const float4*)&Vs[k][ty * 8];
            float4 vb = *(const float4*)&Vs[k][ty * 8 + 4];
            ull ap[8];
            ap[0] = packdup(va.x); ap[1] = packdup(va.y);
            ap[2] = packdup(va.z); ap[3] = packdup(va.w);
            ap[4] = packdup(vb.x); ap[5] = packdup(vb.y);
            ap[6] = packdup(vb.z); ap[7] = packdup(vb.w);
            ull e0 = *(const ull*)&Es[k][tx * 8];
            ull e1 = *(const ull*)&Es[k][tx * 8 + 2];
            ull e2 = *(const ull*)&Es[k][tx * 8 + 4];
            ull e3 = *(const ull*)&Es[k][tx * 8 + 6];
#pragma unroll
            for (int i = 0; i < 8; i++) {
                fma2(acc[i][0], ap[i], e0);
                fma2(acc[i][1], ap[i], e1);
                fma2(acc[i][2], ap[i], e2);
                fma2(acc[i][3], ap[i], e3);
            }
        }
    }
#pragma unroll
    for (int i = 0; i < 8; i++) {
        size_t base = (size_t)(m0 + ty * 8 + i) * NPAD + n0 + tx * 8;
#pragma unroll
        for (int p = 0; p < 4; p++)
            *(ull*)&g_S[base + 2 * p] = acc[i][p];
    }
}

// ---------------- kernel 4: per-row softmax + BCE terms ---------------------
__device__ __forceinline__ float lm_term(float d) {
    // max(log1p(-exp(d)), -100), d = s - lse <= ~0
    float p = __expf(d);
    float r;
    if (p > 1e-4f) r = log1pf(-p);
    else           r = -p * (1.f + p * (0.5f + p * (1.f / 3.f)));
    return fmaxf(r, -100.f);
}

__global__ void row_loss_kernel(const int* __restrict__ facts) {
    int row = blockIdx.x, tid = threadIdx.x;
    const float4* rp = (const float4*)(g_S + (size_t)row * NPAD);

    // pass 1: online max / sum-exp over 50000 = 12500 float4
    float m = -INFINITY, l = 0.f;
    for (int j = tid; j < 12500; j += 256) {
        float4 v = rp[j];
        float mx = fmaxf(fmaxf(v.x, v.y), fmaxf(v.z, v.w));
        float nm = fmaxf(m, mx);
        float le = __expf(v.x - nm) + __expf(v.y - nm) +
                   __expf(v.z - nm) + __expf(v.w - nm);
        l = l * __expf(m - nm) + le;
        m = nm;
    }
    __shared__ float rm[256], rl[256];
    rm[tid] = m; rl[tid] = l; __syncthreads();
    for (int o = 128; o > 0; o >>= 1) {
        if (tid < o) {
            float m2 = rm[tid + o], l2 = rl[tid + o];
            float nm = fmaxf(rm[tid], m2);
            rl[tid] = rl[tid] * __expf(rm[tid] - nm) + l2 * __expf(m2 - nm);
            rm[tid] = nm;
        }
        __syncthreads();
    }
    float lse = rm[0] + logf(rl[0]);

    // pass 2: sum of clamped log1p(-p)
    float accf = 0.f;
    for (int j = tid; j < 12500; j += 256) {
        float4 v = rp[j];
        accf += lm_term(v.x - lse) + lm_term(v.y - lse) +
                lm_term(v.z - lse) + lm_term(v.w - lse);
    }
    double acc = (double)accf;
    if (tid == 0) {
        int y = (row < BSZ) ? facts[3 * row] : facts[3 * (row - BSZ) + 1];
        float sy   = g_S[(size_t)row * NPAD + y];
        float dy   = sy - lse;
        float logp = fmaxf(dy, -100.f);
        acc += (double)logp - (double)lm_term(dy);  // add logp_y, remove log1mp_y
    }
    __shared__ double rd[256];
    rd[tid] = acc; __syncthreads();
    for (int o = 128; o > 0; o >>= 1) {
        if (tid < o) rd[tid] += rd[tid + o];
        __syncthreads();
    }
    if (tid == 0) atomicAdd(&g_acc, rd[0]);
}

// ---------------- kernel 5: finalize ----------------------------------------
__global__ void finalize_kernel(float* out) {
    out[0] = (float)(-g_acc * (1.0 / ((double)BSZ * (double)N_ENT)));
}

// ---------------- launch ----------------------------------------------------
extern "C" void kernel_launch(void* const* d_in, const int* in_sizes, int n_in,
                              void* d_out, int out_size) {
    const int*   facts = (const int*)d_in[0];
    const int*   arch  = (const int*)d_in[1];
    const float* ent_w = (const float*)d_in[2];
    const float* rel_w = (const float*)d_in[3];
    const float* bg_e  = (const float*)d_in[4];
    const float* bb_e  = (const float*)d_in[5];
    const float* bg_r  = (const float*)d_in[6];
    const float* bb_r  = (const float*)d_in[7];
    float* out = (float*)d_out;

    zero_acc_kernel<<<1, 1>>>();
    bn_stats_kernel<<<dim3(256, 3), 256>>>(facts, ent_w, rel_w, bg_e, bb_e, bg_r, bb_r);
    build_vec_kernel<<<BSZ, 256>>>(facts, arch, ent_w, rel_w);
    gemm_kernel<<<dim3(NPAD / BNG, M_ROWS / BMG), 256>>>(ent_w);
    row_loss_kernel<<<M_ROWS, 256>>>(facts);
    finalize_kernel<<<1, 1>>>(out);
}

// round 4
// speedup vs baseline: 2.5791x; 2.5791x over previous
#include <cuda_runtime.h>
#include <cuda_bf16.h>
#include <cuda_fp16.h>
#include <math.h>
#include <stdint.h>

#define N_ENT  50000
#define NDIM   256
#define BSZ    1024
#define M_ROWS 2048
#define NPAD   50048          // 391 * 128

// ---------------- device scratch ----------------
__device__ float          g_scale[768];
__device__ float          g_shift[768];
__device__ __nv_bfloat16  g_Vhi[M_ROWS * NDIM];
__device__ __nv_bfloat16  g_Vlo[M_ROWS * NDIM];
__device__ __nv_bfloat16  g_Ehi[(size_t)NPAD * NDIM];
__device__ __nv_bfloat16  g_Elo[(size_t)NPAD * NDIM];
__device__ __half         g_S[(size_t)M_ROWS * NPAD];   // 205 MB fp16 scores
__device__ double         g_acc;

// ---------------- PTX helpers (sm_103-base-safe: cp.async/ldmatrix/mma) -----
__device__ __forceinline__ uint32_t smem_to_u32(const void* p) {
    uint32_t a;
    asm("{ .reg .u64 t; cvta.to.shared.u64 t, %1; cvt.u32.u64 %0, t; }" : "=r"(a) : "l"(p));
    return a;
}
__device__ __forceinline__ void cp16(uint32_t s, const void* g) {
    asm volatile("cp.async.cg.shared.global [%0], [%1], 16;" :: "r"(s), "l"(g) : "memory");
}
__device__ __forceinline__ void cp_commit() {
    asm volatile("cp.async.commit_group;" ::: "memory");
}
template <int N>
__device__ __forceinline__ void cp_wait() {
    asm volatile("cp.async.wait_group %0;" :: "n"(N) : "memory");
}
__device__ __forceinline__ void ldsm_x4(uint32_t* r, uint32_t a) {
    asm volatile("ldmatrix.sync.aligned.m8n8.x4.shared.b16 {%0,%1,%2,%3}, [%4];"
                 : "=r"(r[0]), "=r"(r[1]), "=r"(r[2]), "=r"(r[3]) : "r"(a));
}
__device__ __forceinline__ void mma16816(float* c, const uint32_t* a, uint32_t b0, uint32_t b1) {
    asm volatile("mma.sync.aligned.m16n8k16.row.col.f32.bf16.bf16.f32 "
                 "{%0,%1,%2,%3}, {%4,%5,%6,%7}, {%8,%9}, {%0,%1,%2,%3};"
                 : "+f"(c[0]), "+f"(c[1]), "+f"(c[2]), "+f"(c[3])
                 : "r"(a[0]), "r"(a[1]), "r"(a[2]), "r"(a[3]), "r"(b0), "r"(b1));
}

// ---------------- kernel 0: zero accumulator ----------------
__global__ void zero_acc_kernel() { g_acc = 0.0; }

// ---------------- kernel 1: batch-norm statistics ----------------
__global__ void bn_stats_kernel(const int* __restrict__ facts,
                                const float* __restrict__ ent_w,
                                const float* __restrict__ rel_w,
                                const float* __restrict__ bg_e,
                                const float* __restrict__ bb_e,
                                const float* __restrict__ bg_r,
                                const float* __restrict__ bb_r) {
    int d = blockIdx.x, s = blockIdx.y, tid = threadIdx.x;
    const float* W = (s == 2) ? rel_w : ent_w;
    float sum = 0.f, sq = 0.f;
    for (int b = tid; b < BSZ; b += 256) {
        int idx = facts[b * 3 + s];
        float x = W[idx * NDIM + d];
        sum += x; sq += x * x;
    }
    __shared__ float s1[256], s2[256];
    s1[tid] = sum; s2[tid] = sq; __syncthreads();
    for (int o = 128; o > 0; o >>= 1) {
        if (tid < o) { s1[tid] += s1[tid + o]; s2[tid] += s2[tid + o]; }
        __syncthreads();
    }
    if (tid == 0) {
        float mean = s1[0] * (1.f / BSZ);
        float var  = s2[0] * (1.f / BSZ) - mean * mean;
        float gamma = (s == 2) ? bg_r[d] : bg_e[d];
        float beta  = (s == 2) ? bb_r[d] : bb_e[d];
        float sc = gamma * rsqrtf(var + 1e-5f);
        g_scale[s * 256 + d] = sc;
        g_shift[s * 256 + d] = beta - mean * sc;
    }
}

// ---------------- kernel 2: head/tail query vectors (bf16 hi/lo out) --------
__global__ void build_vec_kernel(const int* __restrict__ facts,
                                 const int* __restrict__ arch,
                                 const float* __restrict__ ent_w,
                                 const float* __restrict__ rel_w) {
    int b = blockIdx.x, tid = threadIdx.x;
    __shared__ float hen[256], ten[256], ren[256], al[64];
    int h = facts[3 * b], t = facts[3 * b + 1], r = facts[3 * b + 2];
    hen[tid] = ent_w[h * NDIM + tid] * g_scale[tid]       + g_shift[tid];
    ten[tid] = ent_w[t * NDIM + tid] * g_scale[256 + tid] + g_shift[256 + tid];
    ren[tid] = rel_w[r * NDIM + tid] * g_scale[512 + tid] + g_shift[512 + tid];
    if (tid < 64) {
        int a = arch[tid];
        al[tid] = (a == 1) ? 1.f : ((a == 2) ? -1.f : 0.f);
    }
    __syncthreads();
    int k = tid >> 6, l = tid & 63;
    float hv = 0.f, tv = 0.f;
#pragma unroll
    for (int i = 0; i < 4; i++) {
        float rv = ren[i * 64 + l];
#pragma unroll
        for (int j = 0; j < 4; j++) {
            hv += al[i * 16 + j * 4 + k] * rv * ten[j * 64 + l];
            tv += al[i * 16 + k * 4 + j] * rv * hen[j * 64 + l];
        }
    }
    __nv_bfloat16 hh = __float2bfloat16(hv);
    g_Vhi[b * NDIM + tid] = hh;
    g_Vlo[b * NDIM + tid] = __float2bfloat16(hv - __bfloat162float(hh));
    __nv_bfloat16 th = __float2bfloat16(tv);
    g_Vhi[(BSZ + b) * NDIM + tid] = th;
    g_Vlo[(BSZ + b) * NDIM + tid] = __float2bfloat16(tv - __bfloat162float(th));
}

// ---------------- kernel 3: split ent_w into bf16 hi/lo (padded rows = 0) ---
__global__ void convert_e_kernel(const float* __restrict__ E) {
    int t = blockIdx.x * 256 + threadIdx.x;        // 6256*256 threads, 8 floats each
    int row = t >> 5;
    int k8  = (t & 31) * 8;
    float v[8];
    if (row < N_ENT) {
        float4 a = *(const float4*)&E[(size_t)row * NDIM + k8];
        float4 b = *(const float4*)&E[(size_t)row * NDIM + k8 + 4];
        v[0] = a.x; v[1] = a.y; v[2] = a.z; v[3] = a.w;
        v[4] = b.x; v[5] = b.y; v[6] = b.z; v[7] = b.w;
    } else {
#pragma unroll
        for (int i = 0; i < 8; i++) v[i] = 0.f;
    }
    __align__(16) __nv_bfloat16 hb[8], lb[8];
#pragma unroll
    for (int i = 0; i < 8; i++) {
        hb[i] = __float2bfloat16(v[i]);
        lb[i] = __float2bfloat16(v[i] - __bfloat162float(hb[i]));
    }
    *(uint4*)&g_Ehi[(size_t)row * NDIM + k8] = *(uint4*)hb;
    *(uint4*)&g_Elo[(size_t)row * NDIM + k8] = *(uint4*)lb;
}

// ---------------- kernel 4: HMMA GEMM, S = V @ E^T (fp16 out) ---------------
// BM=128, BN=128, BK=64, 2-stage cp.async pipeline, 8 warps (4m x 2n),
// warp tile 32x64, mma.m16n8k16 bf16 -> fp32. Virtual K = 768:
//   seg0: Vhi * Ehi, seg1: Vhi * Elo, seg2: Vlo * Ehi  (Markidis split)
#define SMEM_STAGE   32768            // A 16KB + B 16KB
#define SMEM_TOTAL_GEMM (2 * SMEM_STAGE)

__global__ __launch_bounds__(256, 2) void gemm_kernel() {
    extern __shared__ __align__(128) char smem[];
    uint32_t sbase = smem_to_u32(smem);
    int tid = threadIdx.x, lane = tid & 31, w = tid >> 5;
    int n0g = blockIdx.x * 128, m0 = blockIdx.y * 128;
    int wm = w >> 1, wn = w & 1;

    const __nv_bfloat16* Aseg[3] = { g_Vhi, g_Vhi, g_Vlo };
    const __nv_bfloat16* Bseg[3] = { g_Ehi, g_Elo, g_Ehi };

    float acc[2][8][4];
#pragma unroll
    for (int i = 0; i < 2; i++)
#pragma unroll
        for (int j = 0; j < 8; j++)
#pragma unroll
            for (int q = 0; q < 4; q++) acc[i][j][q] = 0.f;

    // per-thread load map: 4 A-chunks + 4 B-chunks of 16B per stage
    int c_row[4], c_pos[4]; uint32_t c_soff[4];
#pragma unroll
    for (int i = 0; i < 4; i++) {
        int c = tid + i * 256;            // 0..1023
        c_row[i] = c >> 3;                // tile row 0..127
        c_pos[i] = c & 7;                 // 16B chunk in 128B row
        c_soff[i] = (uint32_t)(c_row[i] * 128 + ((c_pos[i] ^ (c_row[i] & 7)) << 4));
    }

    auto load_stage = [&](int kt, int s) {
        int seg = kt >> 2;
        int kk  = (kt & 3) * 64;
        const __nv_bfloat16* Ap = Aseg[seg];
        const __nv_bfloat16* Bp = Bseg[seg];
        uint32_t sA = sbase + (uint32_t)s * SMEM_STAGE;
        uint32_t sB = sA + 16384u;
#pragma unroll
        for (int i = 0; i < 4; i++) {
            cp16(sA + c_soff[i], Ap + (size_t)(m0 + c_row[i]) * NDIM + kk + c_pos[i] * 8);
            cp16(sB + c_soff[i], Bp + (size_t)(n0g + c_row[i]) * NDIM + kk + c_pos[i] * 8);
        }
        cp_commit();
    };

    load_stage(0, 0);

    for (int kt = 0; kt < 12; kt++) {
        int s = kt & 1;
        if (kt < 11) load_stage(kt + 1, s ^ 1);
        if (kt < 11) cp_wait<1>(); else cp_wait<0>();
        __syncthreads();

        uint32_t sA = sbase + (uint32_t)s * SMEM_STAGE;
        uint32_t sB = sA + 16384u;
#pragma unroll
        for (int ks = 0; ks < 4; ks++) {
            uint32_t ar[2][4];
#pragma unroll
            for (int mf = 0; mf < 2; mf++) {
                int row = wm * 32 + mf * 16 + (lane & 15);
                int chunk = ks * 2 + (lane >> 4);
                ldsm_x4(ar[mf], sA + (uint32_t)(row * 128 + ((chunk ^ (row & 7)) << 4)));
            }
            uint32_t br[4][4];
#pragma unroll
            for (int nb = 0; nb < 4; nb++) {
                int n = wn * 64 + nb * 16 + (lane & 7) + ((lane >> 4) & 1) * 8;
                int chunk = ks * 2 + ((lane >> 3) & 1);
                ldsm_x4(br[nb], sB + (uint32_t)(n * 128 + ((chunk ^ (n & 7)) << 4)));
            }
#pragma unroll
            for (int mf = 0; mf < 2; mf++)
#pragma unroll
                for (int nb = 0; nb < 4; nb++) {
                    mma16816(acc[mf][nb * 2],     ar[mf], br[nb][0], br[nb][1]);
                    mma16816(acc[mf][nb * 2 + 1], ar[mf], br[nb][2], br[nb][3]);
                }
        }
        __syncthreads();
    }

    // epilogue: fp32 acc -> fp16 scores, direct global stores
#pragma unroll
    for (int mf = 0; mf < 2; mf++) {
        int r0 = m0 + wm * 32 + mf * 16 + (lane >> 2);
#pragma unroll
        for (int nf = 0; nf < 8; nf++) {
            int col = n0g + wn * 64 + nf * 8 + (lane & 3) * 2;
            __half2 lo = __floats2half2_rn(acc[mf][nf][0], acc[mf][nf][1]);
            __half2 hi = __floats2half2_rn(acc[mf][nf][2], acc[mf][nf][3]);
            __stcs((__half2*)&g_S[(size_t)r0 * NPAD + col], lo);
            __stcs((__half2*)&g_S[(size_t)(r0 + 8) * NPAD + col], hi);
        }
    }
}

// ---------------- kernel 5: per-row softmax + BCE terms (fp16 S) ------------
__device__ __forceinline__ float lm_term(float d) {
    float p = __expf(d);
    float r;
    if (p > 1e-4f) r = log1pf(-p);
    else           r = -p * (1.f + p * (0.5f + p * (1.f / 3.f)));
    return fmaxf(r, -100.f);
}

__global__ void row_loss_kernel(const int* __restrict__ facts) {
    int row = blockIdx.x, tid = threadIdx.x;
    const uint4* rp = (const uint4*)(g_S + (size_t)row * NPAD);

    float m = -INFINITY, l = 0.f;
    for (int j = tid; j < 6250; j += 256) {      // 50000 halves = 6250 uint4
        uint4 v = __ldcs(rp + j);
        float2 p0 = __half22float2(*(__half2*)&v.x);
        float2 p1 = __half22float2(*(__half2*)&v.y);
        float2 p2 = __half22float2(*(__half2*)&v.z);
        float2 p3 = __half22float2(*(__half2*)&v.w);
        float mx = fmaxf(fmaxf(fmaxf(p0.x, p0.y), fmaxf(p1.x, p1.y)),
                         fmaxf(fmaxf(p2.x, p2.y), fmaxf(p3.x, p3.y)));
        float nm = fmaxf(m, mx);
        float le = __expf(p0.x - nm) + __expf(p0.y - nm) +
                   __expf(p1.x - nm) + __expf(p1.y - nm) +
                   __expf(p2.x - nm) + __expf(p2.y - nm) +
                   __expf(p3.x - nm) + __expf(p3.y - nm);
        l = l * __expf(m - nm) + le;
        m = nm;
    }
    __shared__ float rm[256], rl[256];
    rm[tid] = m; rl[tid] = l; __syncthreads();
    for (int o = 128; o > 0; o >>= 1) {
        if (tid < o) {
            float m2 = rm[tid + o], l2 = rl[tid + o];
            float nm = fmaxf(rm[tid], m2);
            rl[tid] = rl[tid] * __expf(rm[tid] - nm) + l2 * __expf(m2 - nm);
            rm[tid] = nm;
        }
        __syncthreads();
    }
    float lse = rm[0] + logf(rl[0]);

    float accf = 0.f;
    for (int j = tid; j < 6250; j += 256) {
        uint4 v = __ldcs(rp + j);
        float2 p0 = __half22float2(*(__half2*)&v.x);
        float2 p1 = __half22float2(*(__half2*)&v.y);
        float2 p2 = __half22float2(*(__half2*)&v.z);
        float2 p3 = __half22float2(*(__half2*)&v.w);
        accf += lm_term(p0.x - lse) + lm_term(p0.y - lse) +
                lm_term(p1.x - lse) + lm_term(p1.y - lse) +
                lm_term(p2.x - lse) + lm_term(p2.y - lse) +
                lm_term(p3.x - lse) + lm_term(p3.y - lse);
    }
    double acc = (double)accf;
    if (tid == 0) {
        int y = (row < BSZ) ? facts[3 * row] : facts[3 * (row - BSZ) + 1];
        float sy = __half2float(g_S[(size_t)row * NPAD + y]);
        float dy = sy - lse;
        float logp = fmaxf(dy, -100.f);
        acc += (double)logp - (double)lm_term(dy);
    }
    __shared__ double rd[256];
    rd[tid] = acc; __syncthreads();
    for (int o = 128; o > 0; o >>= 1) {
        if (tid < o) rd[tid] += rd[tid + o];
        __syncthreads();
    }
    if (tid == 0) atomicAdd(&g_acc, rd[0]);
}

// ---------------- kernel 6: finalize ----------------------------------------
__global__ void finalize_kernel(float* out) {
    out[0] = (float)(-g_acc * (1.0 / ((double)BSZ * (double)N_ENT)));
}

// ---------------- launch ----------------------------------------------------
extern "C" void kernel_launch(void* const* d_in, const int* in_sizes, int n_in,
                              void* d_out, int out_size) {
    const int*   facts = (const int*)d_in[0];
    const int*   arch  = (const int*)d_in[1];
    const float* ent_w = (const float*)d_in[2];
    const float* rel_w = (const float*)d_in[3];
    const float* bg_e  = (const float*)d_in[4];
    const float* bb_e  = (const float*)d_in[5];
    const float* bg_r  = (const float*)d_in[6];
    const float* bb_r  = (const float*)d_in[7];
    float* out = (float*)d_out;

    cudaFuncSetAttribute(gemm_kernel, cudaFuncAttributeMaxDynamicSharedMemorySize,
                         SMEM_TOTAL_GEMM);

    zero_acc_kernel<<<1, 1>>>();
    bn_stats_kernel<<<dim3(256, 3), 256>>>(facts, ent_w, rel_w, bg_e, bb_e, bg_r, bb_r);
    build_vec_kernel<<<BSZ, 256>>>(facts, arch, ent_w, rel_w);
    convert_e_kernel<<<6256, 256>>>(ent_w);
    gemm_kernel<<<dim3(NPAD / 128, M_ROWS / 128), 256, SMEM_TOTAL_GEMM>>>();
    row_loss_kernel<<<M_ROWS, 256>>>(facts);
    finalize_kernel<<<1, 1>>>(out);
}

// round 5
// speedup vs baseline: 4.2761x; 1.6580x over previous
#include <cuda_runtime.h>
#include <cuda_bf16.h>
#include <cuda_fp16.h>
#include <math.h>
#include <stdint.h>

#define N_ENT  50000
#define NDIM   256
#define BSZ    1024
#define M_ROWS 2048
#define NPAD   50048          // 391 * 128

// ---------------- device scratch ----------------
__device__ float          g_scale[768];
__device__ float          g_shift[768];
__device__ __nv_bfloat16  g_Vhi[M_ROWS * NDIM];
__device__ __nv_bfloat16  g_Vlo[M_ROWS * NDIM];
__device__ __nv_bfloat16  g_Ehi[(size_t)NPAD * NDIM];
__device__ __half         g_S[(size_t)M_ROWS * NPAD];   // 205 MB fp16 scores
__device__ double         g_acc;

// ---------------- PTX helpers (sm_103-base-safe) ----------------
__device__ __forceinline__ uint32_t smem_to_u32(const void* p) {
    uint32_t a;
    asm("{ .reg .u64 t; cvta.to.shared.u64 t, %1; cvt.u32.u64 %0, t; }" : "=r"(a) : "l"(p));
    return a;
}
__device__ __forceinline__ void cp16(uint32_t s, const void* g) {
    asm volatile("cp.async.cg.shared.global [%0], [%1], 16;" :: "r"(s), "l"(g) : "memory");
}
__device__ __forceinline__ void cp_commit() {
    asm volatile("cp.async.commit_group;" ::: "memory");
}
template <int N>
__device__ __forceinline__ void cp_wait() {
    asm volatile("cp.async.wait_group %0;" :: "n"(N) : "memory");
}
__device__ __forceinline__ void ldsm_x4(uint32_t* r, uint32_t a) {
    asm volatile("ldmatrix.sync.aligned.m8n8.x4.shared.b16 {%0,%1,%2,%3}, [%4];"
                 : "=r"(r[0]), "=r"(r[1]), "=r"(r[2]), "=r"(r[3]) : "r"(a));
}
__device__ __forceinline__ void mma16816(float* c, const uint32_t* a, uint32_t b0, uint32_t b1) {
    asm volatile("mma.sync.aligned.m16n8k16.row.col.f32.bf16.bf16.f32 "
                 "{%0,%1,%2,%3}, {%4,%5,%6,%7}, {%8,%9}, {%0,%1,%2,%3};"
                 : "+f"(c[0]), "+f"(c[1]), "+f"(c[2]), "+f"(c[3])
                 : "r"(a[0]), "r"(a[1]), "r"(a[2]), "r"(a[3]), "r"(b0), "r"(b1));
}

// ---------------- kernel 0: zero accumulator ----------------
__global__ void zero_acc_kernel() { g_acc = 0.0; }

// ---------------- kernel 1: batch-norm statistics ----------------
__global__ void bn_stats_kernel(const int* __restrict__ facts,
                                const float* __restrict__ ent_w,
                                const float* __restrict__ rel_w,
                                const float* __restrict__ bg_e,
                                const float* __restrict__ bb_e,
                                const float* __restrict__ bg_r,
                                const float* __restrict__ bb_r) {
    int d = blockIdx.x, s = blockIdx.y, tid = threadIdx.x;
    const float* W = (s == 2) ? rel_w : ent_w;
    float sum = 0.f, sq = 0.f;
    for (int b = tid; b < BSZ; b += 256) {
        int idx = facts[b * 3 + s];
        float x = W[idx * NDIM + d];
        sum += x; sq += x * x;
    }
    __shared__ float s1[256], s2[256];
    s1[tid] = sum; s2[tid] = sq; __syncthreads();
    for (int o = 128; o > 0; o >>= 1) {
        if (tid < o) { s1[tid] += s1[tid + o]; s2[tid] += s2[tid + o]; }
        __syncthreads();
    }
    if (tid == 0) {
        float mean = s1[0] * (1.f / BSZ);
        float var  = s2[0] * (1.f / BSZ) - mean * mean;
        float gamma = (s == 2) ? bg_r[d] : bg_e[d];
        float beta  = (s == 2) ? bb_r[d] : bb_e[d];
        float sc = gamma * rsqrtf(var + 1e-5f);
        g_scale[s * 256 + d] = sc;
        g_shift[s * 256 + d] = beta - mean * sc;
    }
}

// ---------------- kernel 2: head/tail query vectors (bf16 hi/lo out) --------
__global__ void build_vec_kernel(const int* __restrict__ facts,
                                 const int* __restrict__ arch,
                                 const float* __restrict__ ent_w,
                                 const float* __restrict__ rel_w) {
    int b = blockIdx.x, tid = threadIdx.x;
    __shared__ float hen[256], ten[256], ren[256], al[64];
    int h = facts[3 * b], t = facts[3 * b + 1], r = facts[3 * b + 2];
    hen[tid] = ent_w[h * NDIM + tid] * g_scale[tid]       + g_shift[tid];
    ten[tid] = ent_w[t * NDIM + tid] * g_scale[256 + tid] + g_shift[256 + tid];
    ren[tid] = rel_w[r * NDIM + tid] * g_scale[512 + tid] + g_shift[512 + tid];
    if (tid < 64) {
        int a = arch[tid];
        al[tid] = (a == 1) ? 1.f : ((a == 2) ? -1.f : 0.f);
    }
    __syncthreads();
    int k = tid >> 6, l = tid & 63;
    float hv = 0.f, tv = 0.f;
#pragma unroll
    for (int i = 0; i < 4; i++) {
        float rv = ren[i * 64 + l];
#pragma unroll
        for (int j = 0; j < 4; j++) {
            hv += al[i * 16 + j * 4 + k] * rv * ten[j * 64 + l];
            tv += al[i * 16 + k * 4 + j] * rv * hen[j * 64 + l];
        }
    }
    __nv_bfloat16 hh = __float2bfloat16(hv);
    g_Vhi[b * NDIM + tid] = hh;
    g_Vlo[b * NDIM + tid] = __float2bfloat16(hv - __bfloat162float(hh));
    __nv_bfloat16 th = __float2bfloat16(tv);
    g_Vhi[(BSZ + b) * NDIM + tid] = th;
    g_Vlo[(BSZ + b) * NDIM + tid] = __float2bfloat16(tv - __bfloat162float(th));
}

// ---------------- kernel 3: ent_w -> bf16 hi only (padded rows = 0) ---------
__global__ void convert_e_kernel(const float* __restrict__ E) {
    int t = blockIdx.x * 256 + threadIdx.x;
    int row = t >> 5;
    int k8  = (t & 31) * 8;
    float v[8];
    if (row < N_ENT) {
        float4 a = *(const float4*)&E[(size_t)row * NDIM + k8];
        float4 b = *(const float4*)&E[(size_t)row * NDIM + k8 + 4];
        v[0] = a.x; v[1] = a.y; v[2] = a.z; v[3] = a.w;
        v[4] = b.x; v[5] = b.y; v[6] = b.z; v[7] = b.w;
    } else {
#pragma unroll
        for (int i = 0; i < 8; i++) v[i] = 0.f;
    }
    __align__(16) __nv_bfloat16 hb[8];
#pragma unroll
    for (int i = 0; i < 8; i++) hb[i] = __float2bfloat16(v[i]);
    *(uint4*)&g_Ehi[(size_t)row * NDIM + k8] = *(uint4*)hb;
}

// ---------------- kernel 4: HMMA GEMM, S = V @ Ehi^T (fp16 out) -------------
// BM=128, BN=128, BK=64. Stage = Ahi 16K + Alo 16K + B 16K = 48KB, 2 stages.
// 8 warps (4m x 2n), warp tile 32x64. Per k16-step: B frags shared between
// the Vhi and Vlo MMA groups (2-term Markidis, same accumulators).
#define SMEM_STAGE   49152
#define SMEM_TOTAL_GEMM (2 * SMEM_STAGE)

__global__ __launch_bounds__(256, 2) void gemm_kernel() {
    extern __shared__ __align__(128) char smem[];
    uint32_t sbase = smem_to_u32(smem);
    int tid = threadIdx.x, lane = tid & 31, w = tid >> 5;
    int n0g = blockIdx.x * 128, m0 = blockIdx.y * 128;
    int wm = w >> 1, wn = w & 1;

    float acc[2][8][4];
#pragma unroll
    for (int i = 0; i < 2; i++)
#pragma unroll
        for (int j = 0; j < 8; j++)
#pragma unroll
            for (int q = 0; q < 4; q++) acc[i][j][q] = 0.f;

    int c_row[4], c_pos[4]; uint32_t c_soff[4];
#pragma unroll
    for (int i = 0; i < 4; i++) {
        int c = tid + i * 256;
        c_row[i] = c >> 3;
        c_pos[i] = c & 7;
        c_soff[i] = (uint32_t)(c_row[i] * 128 + ((c_pos[i] ^ (c_row[i] & 7)) << 4));
    }

    auto load_stage = [&](int kt, int s) {
        int kk = kt * 64;
        uint32_t sAh = sbase + (uint32_t)s * SMEM_STAGE;
        uint32_t sAl = sAh + 16384u;
        uint32_t sB  = sAh + 32768u;
#pragma unroll
        for (int i = 0; i < 4; i++) {
            cp16(sAh + c_soff[i], g_Vhi + (size_t)(m0 + c_row[i]) * NDIM + kk + c_pos[i] * 8);
            cp16(sAl + c_soff[i], g_Vlo + (size_t)(m0 + c_row[i]) * NDIM + kk + c_pos[i] * 8);
            cp16(sB  + c_soff[i], g_Ehi + (size_t)(n0g + c_row[i]) * NDIM + kk + c_pos[i] * 8);
        }
        cp_commit();
    };

    load_stage(0, 0);

    for (int kt = 0; kt < 4; kt++) {
        int s = kt & 1;
        if (kt < 3) load_stage(kt + 1, s ^ 1);
        if (kt < 3) cp_wait<1>(); else cp_wait<0>();
        __syncthreads();

        uint32_t sAh = sbase + (uint32_t)s * SMEM_STAGE;
        uint32_t sAl = sAh + 16384u;
        uint32_t sB  = sAh + 32768u;
#pragma unroll
        for (int ks = 0; ks < 4; ks++) {
            uint32_t br[4][4];
#pragma unroll
            for (int nb = 0; nb < 4; nb++) {
                int n = wn * 64 + nb * 16 + (lane & 7) + ((lane >> 4) & 1) * 8;
                int chunk = ks * 2 + ((lane >> 3) & 1);
                ldsm_x4(br[nb], sB + (uint32_t)(n * 128 + ((chunk ^ (n & 7)) << 4)));
            }
            uint32_t ar[2][4];
            // --- Vhi pass ---
#pragma unroll
            for (int mf = 0; mf < 2; mf++) {
                int row = wm * 32 + mf * 16 + (lane & 15);
                int chunk = ks * 2 + (lane >> 4);
                ldsm_x4(ar[mf], sAh + (uint32_t)(row * 128 + ((chunk ^ (row & 7)) << 4)));
            }
#pragma unroll
            for (int mf = 0; mf < 2; mf++)
#pragma unroll
                for (int nb = 0; nb < 4; nb++) {
                    mma16816(acc[mf][nb * 2],     ar[mf], br[nb][0], br[nb][1]);
                    mma16816(acc[mf][nb * 2 + 1], ar[mf], br[nb][2], br[nb][3]);
                }
            // --- Vlo pass (same B frags, same accumulators) ---
#pragma unroll
            for (int mf = 0; mf < 2; mf++) {
                int row = wm * 32 + mf * 16 + (lane & 15);
                int chunk = ks * 2 + (lane >> 4);
                ldsm_x4(ar[mf], sAl + (uint32_t)(row * 128 + ((chunk ^ (row & 7)) << 4)));
            }
#pragma unroll
            for (int mf = 0; mf < 2; mf++)
#pragma unroll
                for (int nb = 0; nb < 4; nb++) {
                    mma16816(acc[mf][nb * 2],     ar[mf], br[nb][0], br[nb][1]);
                    mma16816(acc[mf][nb * 2 + 1], ar[mf], br[nb][2], br[nb][3]);
                }
        }
        __syncthreads();
    }

    // epilogue: fp32 acc -> fp16 scores
#pragma unroll
    for (int mf = 0; mf < 2; mf++) {
        int r0 = m0 + wm * 32 + mf * 16 + (lane >> 2);
#pragma unroll
        for (int nf = 0; nf < 8; nf++) {
            int col = n0g + wn * 64 + nf * 8 + (lane & 3) * 2;
            __half2 lo = __floats2half2_rn(acc[mf][nf][0], acc[mf][nf][1]);
            __half2 hi = __floats2half2_rn(acc[mf][nf][2], acc[mf][nf][3]);
            __stcs((__half2*)&g_S[(size_t)r0 * NPAD + col], lo);
            __stcs((__half2*)&g_S[(size_t)(r0 + 8) * NPAD + col], hi);
        }
    }
}

// ---------------- kernel 5: single-pass softmax moments + BCE ---------------
// sum_e log1p(-p_e) = -(1 + S2/2 + S3/3 + S4/4),  Sk = sum p^k  (p_max ~ 1e-2)
__global__ void row_loss_kernel(const int* __restrict__ facts) {
    int row = blockIdx.x, tid = threadIdx.x;
    const uint4* rp = (const uint4*)(g_S + (size_t)row * NPAD);

    float m = -INFINITY, l1 = 0.f, l2 = 0.f, l3 = 0.f, l4 = 0.f;
    for (int j = tid; j < 6250; j += 256) {      // 50000 halves = 6250 uint4
        uint4 v = __ldcs(rp + j);
        float2 p0 = __half22float2(*(__half2*)&v.x);
        float2 p1 = __half22float2(*(__half2*)&v.y);
        float2 p2 = __half22float2(*(__half2*)&v.z);
        float2 p3 = __half22float2(*(__half2*)&v.w);
        float s[8] = { p0.x, p0.y, p1.x, p1.y, p2.x, p2.y, p3.x, p3.y };
        float mx = s[0];
#pragma unroll
        for (int i = 1; i < 8; i++) mx = fmaxf(mx, s[i]);
        float nm = fmaxf(m, mx);
        float r  = __expf(m - nm);
        float r2 = r * r;
        float a1 = 0.f, a2 = 0.f, a3 = 0.f, a4 = 0.f;
#pragma unroll
        for (int i = 0; i < 8; i++) {
            float e  = __expf(s[i] - nm);
            float e2 = e * e;
            a1 += e; a2 += e2; a3 += e2 * e; a4 += e2 * e2;
        }
        l1 = l1 * r + a1;
        l2 = l2 * r2 + a2;
        l3 = l3 * r2 * r + a3;
        l4 = l4 * r2 * r2 + a4;
        m = nm;
    }
    __shared__ float rm[256], r1[256], r2s[256], r3s[256], r4s[256];
    rm[tid] = m; r1[tid] = l1; r2s[tid] = l2; r3s[tid] = l3; r4s[tid] = l4;
    __syncthreads();
    for (int o = 128; o > 0; o >>= 1) {
        if (tid < o) {
            float ma = rm[tid], mb = rm[tid + o];
            float nm = fmaxf(ma, mb);
            float ra = __expf(ma - nm), rb = __expf(mb - nm);
            float ra2 = ra * ra, rb2 = rb * rb;
            r1[tid]  = r1[tid]  * ra        + r1[tid + o]  * rb;
            r2s[tid] = r2s[tid] * ra2       + r2s[tid + o] * rb2;
            r3s[tid] = r3s[tid] * ra2 * ra  + r3s[tid + o] * rb2 * rb;
            r4s[tid] = r4s[tid] * ra2 * ra2 + r4s[tid + o] * rb2 * rb2;
            rm[tid] = nm;
        }
        __syncthreads();
    }
    if (tid == 0) {
        float L1 = r1[0];
        float lse = rm[0] + logf(L1);
        float inv = 1.f / L1;
        float S2 = r2s[0] * inv * inv;
        float S3 = r3s[0] * inv * inv * inv;
        float S4 = r4s[0] * inv * inv * inv * inv;
        float sum_lm = -(1.f + 0.5f * S2 + (1.f / 3.f) * S3 + 0.25f * S4);

        int y = (row < BSZ) ? facts[3 * row] : facts[3 * (row - BSZ) + 1];
        float sy = __half2float(g_S[(size_t)row * NPAD + y]);
        float dy = sy - lse;
        float logp = fmaxf(dy, -100.f);
        float py = __expf(dy);
        float lm_y = fmaxf(log1pf(-py), -100.f);
        double acc = (double)sum_lm + (double)logp - (double)lm_y;
        atomicAdd(&g_acc, acc);
    }
}

// ---------------- kernel 6: finalize ----------------------------------------
__global__ void finalize_kernel(float* out) {
    out[0] = (float)(-g_acc * (1.0 / ((double)BSZ * (double)N_ENT)));
}

// ---------------- launch ----------------------------------------------------
extern "C" void kernel_launch(void* const* d_in, const int* in_sizes, int n_in,
                              void* d_out, int out_size) {
    const int*   facts = (const int*)d_in[0];
    const int*   arch  = (const int*)d_in[1];
    const float* ent_w = (const float*)d_in[2];
    const float* rel_w = (const float*)d_in[3];
    const float* bg_e  = (const float*)d_in[4];
    const float* bb_e  = (const float*)d_in[5];
    const float* bg_r  = (const float*)d_in[6];
    const float* bb_r  = (const float*)d_in[7];
    float* out = (float*)d_out;

    cudaFuncSetAttribute(gemm_kernel, cudaFuncAttributeMaxDynamicSharedMemorySize,
                         SMEM_TOTAL_GEMM);

    zero_acc_kernel<<<1, 1>>>();
    bn_stats_kernel<<<dim3(256, 3), 256>>>(facts, ent_w, rel_w, bg_e, bb_e, bg_r, bb_r);
    build_vec_kernel<<<BSZ, 256>>>(facts, arch, ent_w, rel_w);
    convert_e_kernel<<<6256, 256>>>(ent_w);
    gemm_kernel<<<dim3(NPAD / 128, M_ROWS / 128), 256, SMEM_TOTAL_GEMM>>>();
    row_loss_kernel<<<M_ROWS, 256>>>(facts);
    finalize_kernel<<<1, 1>>>(out);
}

// round 6
// speedup vs baseline: 5.0266x; 1.1755x over previous
#include <cuda_runtime.h>
#include <cuda_bf16.h>
#include <cuda_fp16.h>
#include <math.h>
#include <stdint.h>

#define N_ENT  50000
#define NDIM   256
#define BSZ    1024
#define M_ROWS 2048
#define NPAD   50048          // 391 * 128

// ---------------- device scratch ----------------
__device__ float          g_scale[768];
__device__ float          g_shift[768];
__device__ __nv_bfloat16  g_Vhi[M_ROWS * NDIM];
__device__ __nv_bfloat16  g_Vlo[M_ROWS * NDIM];
__device__ __nv_bfloat16  g_Ehi[(size_t)NPAD * NDIM];
__device__ float          g_L1[M_ROWS];
__device__ float          g_L2[M_ROWS];
__device__ float          g_L3[M_ROWS];
__device__ float          g_sy[M_ROWS];

// ---------------- PTX helpers (sm_103-base-safe) ----------------
__device__ __forceinline__ uint32_t smem_to_u32(const void* p) {
    uint32_t a;
    asm("{ .reg .u64 t; cvta.to.shared.u64 t, %1; cvt.u32.u64 %0, t; }" : "=r"(a) : "l"(p));
    return a;
}
__device__ __forceinline__ void cp16(uint32_t s, const void* g) {
    asm volatile("cp.async.cg.shared.global [%0], [%1], 16;" :: "r"(s), "l"(g) : "memory");
}
__device__ __forceinline__ void cp_commit() {
    asm volatile("cp.async.commit_group;" ::: "memory");
}
template <int N>
__device__ __forceinline__ void cp_wait() {
    asm volatile("cp.async.wait_group %0;" :: "n"(N) : "memory");
}
__device__ __forceinline__ void ldsm_x4(uint32_t* r, uint32_t a) {
    asm volatile("ldmatrix.sync.aligned.m8n8.x4.shared.b16 {%0,%1,%2,%3}, [%4];"
                 : "=r"(r[0]), "=r"(r[1]), "=r"(r[2]), "=r"(r[3]) : "r"(a));
}
__device__ __forceinline__ void mma16816(float* c, const uint32_t* a, uint32_t b0, uint32_t b1) {
    asm volatile("mma.sync.aligned.m16n8k16.row.col.f32.bf16.bf16.f32 "
                 "{%0,%1,%2,%3}, {%4,%5,%6,%7}, {%8,%9}, {%0,%1,%2,%3};"
                 : "+f"(c[0]), "+f"(c[1]), "+f"(c[2]), "+f"(c[3])
                 : "r"(a[0]), "r"(a[1]), "r"(a[2]), "r"(a[3]), "r"(b0), "r"(b1));
}

// ---------------- kernel 0: zero the row accumulators -----------------------
__global__ void zero_kernel() {
    int t = blockIdx.x * 256 + threadIdx.x;
    for (int i = t; i < M_ROWS; i += gridDim.x * 256) {
        g_L1[i] = 0.f; g_L2[i] = 0.f; g_L3[i] = 0.f;
    }
}

// ---------------- kernel 1: batch-norm statistics ----------------
__global__ void bn_stats_kernel(const int* __restrict__ facts,
                                const float* __restrict__ ent_w,
                                const float* __restrict__ rel_w,
                                const float* __restrict__ bg_e,
                                const float* __restrict__ bb_e,
                                const float* __restrict__ bg_r,
                                const float* __restrict__ bb_r) {
    int d = blockIdx.x, s = blockIdx.y, tid = threadIdx.x;
    const float* W = (s == 2) ? rel_w : ent_w;
    float sum = 0.f, sq = 0.f;
    for (int b = tid; b < BSZ; b += 256) {
        int idx = facts[b * 3 + s];
        float x = W[idx * NDIM + d];
        sum += x; sq += x * x;
    }
    __shared__ float s1[256], s2[256];
    s1[tid] = sum; s2[tid] = sq; __syncthreads();
    for (int o = 128; o > 0; o >>= 1) {
        if (tid < o) { s1[tid] += s1[tid + o]; s2[tid] += s2[tid + o]; }
        __syncthreads();
    }
    if (tid == 0) {
        float mean = s1[0] * (1.f / BSZ);
        float var  = s2[0] * (1.f / BSZ) - mean * mean;
        float gamma = (s == 2) ? bg_r[d] : bg_e[d];
        float beta  = (s == 2) ? bb_r[d] : bb_e[d];
        float sc = gamma * rsqrtf(var + 1e-5f);
        g_scale[s * 256 + d] = sc;
        g_shift[s * 256 + d] = beta - mean * sc;
    }
}

// ---------------- kernel 2: head/tail query vectors (bf16 hi/lo out) --------
__global__ void build_vec_kernel(const int* __restrict__ facts,
                                 const int* __restrict__ arch,
                                 const float* __restrict__ ent_w,
                                 const float* __restrict__ rel_w) {
    int b = blockIdx.x, tid = threadIdx.x;
    __shared__ float hen[256], ten[256], ren[256], al[64];
    int h = facts[3 * b], t = facts[3 * b + 1], r = facts[3 * b + 2];
    hen[tid] = ent_w[h * NDIM + tid] * g_scale[tid]       + g_shift[tid];
    ten[tid] = ent_w[t * NDIM + tid] * g_scale[256 + tid] + g_shift[256 + tid];
    ren[tid] = rel_w[r * NDIM + tid] * g_scale[512 + tid] + g_shift[512 + tid];
    if (tid < 64) {
        int a = arch[tid];
        al[tid] = (a == 1) ? 1.f : ((a == 2) ? -1.f : 0.f);
    }
    __syncthreads();
    int k = tid >> 6, l = tid & 63;
    float hv = 0.f, tv = 0.f;
#pragma unroll
    for (int i = 0; i < 4; i++) {
        float rv = ren[i * 64 + l];
#pragma unroll
        for (int j = 0; j < 4; j++) {
            hv += al[i * 16 + j * 4 + k] * rv * ten[j * 64 + l];
            tv += al[i * 16 + k * 4 + j] * rv * hen[j * 64 + l];
        }
    }
    __nv_bfloat16 hh = __float2bfloat16(hv);
    g_Vhi[b * NDIM + tid] = hh;
    g_Vlo[b * NDIM + tid] = __float2bfloat16(hv - __bfloat162float(hh));
    __nv_bfloat16 th = __float2bfloat16(tv);
    g_Vhi[(BSZ + b) * NDIM + tid] = th;
    g_Vlo[(BSZ + b) * NDIM + tid] = __float2bfloat16(tv - __bfloat162float(th));
}

// ---------------- kernel 3: ent_w -> bf16 hi only (padded rows = 0) ---------
__global__ void convert_e_kernel(const float* __restrict__ E) {
    int t = blockIdx.x * 256 + threadIdx.x;
    int row = t >> 5;
    int k8  = (t & 31) * 8;
    float v[8];
    if (row < N_ENT) {
        float4 a = *(const float4*)&E[(size_t)row * NDIM + k8];
        float4 b = *(const float4*)&E[(size_t)row * NDIM + k8 + 4];
        v[0] = a.x; v[1] = a.y; v[2] = a.z; v[3] = a.w;
        v[4] = b.x; v[5] = b.y; v[6] = b.z; v[7] = b.w;
    } else {
#pragma unroll
        for (int i = 0; i < 8; i++) v[i] = 0.f;
    }
    __align__(16) __nv_bfloat16 hb[8];
#pragma unroll
    for (int i = 0; i < 8; i++) hb[i] = __float2bfloat16(v[i]);
    *(uint4*)&g_Ehi[(size_t)row * NDIM + k8] = *(uint4*)hb;
}

// ---------------- kernel 4: HMMA GEMM + fused moment epilogue ---------------
// BM=128, BN=128, BK=64, 2-stage cp.async, 8 warps (4m x 2n), warp tile 32x64.
// 2-term Markidis: (Vhi + Vlo) @ Ehi, shared B frags, same accumulators.
// Epilogue: e = exp(s - 16) per score; accumulate L1/L2/L3 per row via
// shfl-reduce + atomicAdd. No score matrix is materialized.
#define SMEM_STAGE   49152
#define SMEM_TOTAL_GEMM (2 * SMEM_STAGE)
#define SHIFT16_LOG2 23.083120654223414f   // 16 * log2(e)

__global__ __launch_bounds__(256, 2) void gemm_kernel() {
    extern __shared__ __align__(128) char smem[];
    uint32_t sbase = smem_to_u32(smem);
    int tid = threadIdx.x, lane = tid & 31, w = tid >> 5;
    int n0g = blockIdx.x * 128, m0 = blockIdx.y * 128;
    int wm = w >> 1, wn = w & 1;

    float acc[2][8][4];
#pragma unroll
    for (int i = 0; i < 2; i++)
#pragma unroll
        for (int j = 0; j < 8; j++)
#pragma unroll
            for (int q = 0; q < 4; q++) acc[i][j][q] = 0.f;

    int c_row[4], c_pos[4]; uint32_t c_soff[4];
#pragma unroll
    for (int i = 0; i < 4; i++) {
        int c = tid + i * 256;
        c_row[i] = c >> 3;
        c_pos[i] = c & 7;
        c_soff[i] = (uint32_t)(c_row[i] * 128 + ((c_pos[i] ^ (c_row[i] & 7)) << 4));
    }

    auto load_stage = [&](int kt, int s) {
        int kk = kt * 64;
        uint32_t sAh = sbase + (uint32_t)s * SMEM_STAGE;
        uint32_t sAl = sAh + 16384u;
        uint32_t sB  = sAh + 32768u;
#pragma unroll
        for (int i = 0; i < 4; i++) {
            cp16(sAh + c_soff[i], g_Vhi + (size_t)(m0 + c_row[i]) * NDIM + kk + c_pos[i] * 8);
            cp16(sAl + c_soff[i], g_Vlo + (size_t)(m0 + c_row[i]) * NDIM + kk + c_pos[i] * 8);
            cp16(sB  + c_soff[i], g_Ehi + (size_t)(n0g + c_row[i]) * NDIM + kk + c_pos[i] * 8);
        }
        cp_commit();
    };

    load_stage(0, 0);

    for (int kt = 0; kt < 4; kt++) {
        int s = kt & 1;
        if (kt < 3) load_stage(kt + 1, s ^ 1);
        if (kt < 3) cp_wait<1>(); else cp_wait<0>();
        __syncthreads();

        uint32_t sAh = sbase + (uint32_t)s * SMEM_STAGE;
        uint32_t sAl = sAh + 16384u;
        uint32_t sB  = sAh + 32768u;
#pragma unroll
        for (int ks = 0; ks < 4; ks++) {
            uint32_t br[4][4];
#pragma unroll
            for (int nb = 0; nb < 4; nb++) {
                int n = wn * 64 + nb * 16 + (lane & 7) + ((lane >> 4) & 1) * 8;
                int chunk = ks * 2 + ((lane >> 3) & 1);
                ldsm_x4(br[nb], sB + (uint32_t)(n * 128 + ((chunk ^ (n & 7)) << 4)));
            }
            uint32_t ar[2][4];
#pragma unroll
            for (int mf = 0; mf < 2; mf++) {
                int row = wm * 32 + mf * 16 + (lane & 15);
                int chunk = ks * 2 + (lane >> 4);
                ldsm_x4(ar[mf], sAh + (uint32_t)(row * 128 + ((chunk ^ (row & 7)) << 4)));
            }
#pragma unroll
            for (int mf = 0; mf < 2; mf++)
#pragma unroll
                for (int nb = 0; nb < 4; nb++) {
                    mma16816(acc[mf][nb * 2],     ar[mf], br[nb][0], br[nb][1]);
                    mma16816(acc[mf][nb * 2 + 1], ar[mf], br[nb][2], br[nb][3]);
                }
#pragma unroll
            for (int mf = 0; mf < 2; mf++) {
                int row = wm * 32 + mf * 16 + (lane & 15);
                int chunk = ks * 2 + (lane >> 4);
                ldsm_x4(ar[mf], sAl + (uint32_t)(row * 128 + ((chunk ^ (row & 7)) << 4)));
            }
#pragma unroll
            for (int mf = 0; mf < 2; mf++)
#pragma unroll
                for (int nb = 0; nb < 4; nb++) {
                    mma16816(acc[mf][nb * 2],     ar[mf], br[nb][0], br[nb][1]);
                    mma16816(acc[mf][nb * 2 + 1], ar[mf], br[nb][2], br[nb][3]);
                }
        }
        __syncthreads();
    }

    // ---- fused epilogue: per-row moments, e = exp(s - 16) ----
    bool edge = (n0g + 128 > N_ENT);
#pragma unroll
    for (int mf = 0; mf < 2; mf++) {
#pragma unroll
        for (int half = 0; half < 2; half++) {
            float a1 = 0.f, a2 = 0.f, a3 = 0.f;
#pragma unroll
            for (int nf = 0; nf < 8; nf++) {
                int col = n0g + wn * 64 + nf * 8 + (lane & 3) * 2;
                float s0 = acc[mf][nf][half * 2];
                float s1 = acc[mf][nf][half * 2 + 1];
                if (!edge || col < N_ENT) {
                    float e = exp2f(fmaf(s0, 1.44269504f, -SHIFT16_LOG2));
                    a1 += e; float e2 = e * e; a2 += e2; a3 += e2 * e;
                }
                if (!edge || col + 1 < N_ENT) {
                    float e = exp2f(fmaf(s1, 1.44269504f, -SHIFT16_LOG2));
                    a1 += e; float e2 = e * e; a2 += e2; a3 += e2 * e;
                }
            }
            a1 += __shfl_xor_sync(0xffffffffu, a1, 1);
            a2 += __shfl_xor_sync(0xffffffffu, a2, 1);
            a3 += __shfl_xor_sync(0xffffffffu, a3, 1);
            a1 += __shfl_xor_sync(0xffffffffu, a1, 2);
            a2 += __shfl_xor_sync(0xffffffffu, a2, 2);
            a3 += __shfl_xor_sync(0xffffffffu, a3, 2);
            if ((lane & 3) == 0) {
                int row = m0 + wm * 32 + mf * 16 + half * 8 + (lane >> 2);
                atomicAdd(&g_L1[row], a1);
                atomicAdd(&g_L2[row], a2);
                atomicAdd(&g_L3[row], a3);
            }
        }
    }
}

// ---------------- kernel 5: exact label scores (one warp per row) -----------
__global__ void sy_kernel(const int* __restrict__ facts) {
    int gw   = (blockIdx.x * 256 + threadIdx.x) >> 5;
    int lane = threadIdx.x & 31;
    if (gw >= M_ROWS) return;
    int y = (gw < BSZ) ? facts[3 * gw] : facts[3 * (gw - BSZ) + 1];
    const __nv_bfloat16* vh = &g_Vhi[gw * NDIM];
    const __nv_bfloat16* vl = &g_Vlo[gw * NDIM];
    const __nv_bfloat16* ee = &g_Ehi[(size_t)y * NDIM];
    float s = 0.f;
    uint4 uh = *(const uint4*)&vh[lane * 8];
    uint4 ul = *(const uint4*)&vl[lane * 8];
    uint4 ue = *(const uint4*)&ee[lane * 8];
    const __nv_bfloat16* ph = (const __nv_bfloat16*)&uh;
    const __nv_bfloat16* pl = (const __nv_bfloat16*)&ul;
    const __nv_bfloat16* pe = (const __nv_bfloat16*)&ue;
#pragma unroll
    for (int i = 0; i < 8; i++)
        s += (__bfloat162float(ph[i]) + __bfloat162float(pl[i])) * __bfloat162float(pe[i]);
#pragma unroll
    for (int o = 16; o > 0; o >>= 1) s += __shfl_xor_sync(0xffffffffu, s, o);
    if (lane == 0) g_sy[gw] = s;
}

// ---------------- kernel 6: finalize loss from (L1,L2,L3,sy) ----------------
__global__ void finalize_kernel(float* out) {
    int tid = threadIdx.x;
    double acc = 0.0;
    for (int r = tid; r < M_ROWS; r += 256) {
        float L1 = g_L1[r];
        float lse = 16.f + logf(L1);
        float inv = 1.f / L1;
        float S2 = g_L2[r] * inv * inv;
        float S3 = g_L3[r] * inv * inv * inv;
        float sum_lm = -(1.f + 0.5f * S2 + (1.f / 3.f) * S3);
        float dy = g_sy[r] - lse;
        float logp = fmaxf(dy, -100.f);
        float py = __expf(dy);
        float lm_y = fmaxf(log1pf(-py), -100.f);
        acc += (double)sum_lm + (double)logp - (double)lm_y;
    }
    __shared__ double rd[256];
    rd[tid] = acc; __syncthreads();
    for (int o = 128; o > 0; o >>= 1) {
        if (tid < o) rd[tid] += rd[tid + o];
        __syncthreads();
    }
    if (tid == 0)
        out[0] = (float)(-rd[0] * (1.0 / ((double)BSZ * (double)N_ENT)));
}

// ---------------- launch ----------------------------------------------------
extern "C" void kernel_launch(void* const* d_in, const int* in_sizes, int n_in,
                              void* d_out, int out_size) {
    const int*   facts = (const int*)d_in[0];
    const int*   arch  = (const int*)d_in[1];
    const float* ent_w = (const float*)d_in[2];
    const float* rel_w = (const float*)d_in[3];
    const float* bg_e  = (const float*)d_in[4];
    const float* bb_e  = (const float*)d_in[5];
    const float* bg_r  = (const float*)d_in[6];
    const float* bb_r  = (const float*)d_in[7];
    float* out = (float*)d_out;

    cudaFuncSetAttribute(gemm_kernel, cudaFuncAttributeMaxDynamicSharedMemorySize,
                         SMEM_TOTAL_GEMM);

    zero_kernel<<<8, 256>>>();
    bn_stats_kernel<<<dim3(256, 3), 256>>>(facts, ent_w, rel_w, bg_e, bb_e, bg_r, bb_r);
    build_vec_kernel<<<BSZ, 256>>>(facts, arch, ent_w, rel_w);
    convert_e_kernel<<<6256, 256>>>(ent_w);
    gemm_kernel<<<dim3(NPAD / 128, M_ROWS / 128), 256, SMEM_TOTAL_GEMM>>>();
    sy_kernel<<<256, 256>>>(facts);
    finalize_kernel<<<1, 256>>>(out);
}

// round 7
// speedup vs baseline: 7.8960x; 1.5709x over previous
#include <cuda_runtime.h>
#include <cuda_bf16.h>
#include <cuda_fp16.h>
#include <math.h>
#include <stdint.h>

#define N_ENT  50000
#define NDIM   256
#define BSZ    1024
#define M_ROWS 2048
#define NPAD   50048          // 391 * 128

// ---------------- device scratch ----------------
__device__ float          g_scale[768];
__device__ float          g_shift[768];
__device__ __nv_bfloat16  g_Vhi[M_ROWS * NDIM];
__device__ __nv_bfloat16  g_Vlo[M_ROWS * NDIM];
__device__ __nv_bfloat16  g_Ehi[(size_t)NPAD * NDIM];
__device__ float          g_L1[M_ROWS];
__device__ float          g_L2[M_ROWS];
__device__ float          g_sy[M_ROWS];

// ---------------- PTX helpers (sm_103-base-safe) ----------------
__device__ __forceinline__ uint32_t smem_to_u32(const void* p) {
    uint32_t a;
    asm("{ .reg .u64 t; cvta.to.shared.u64 t, %1; cvt.u32.u64 %0, t; }" : "=r"(a) : "l"(p));
    return a;
}
__device__ __forceinline__ void cp16(uint32_t s, const void* g) {
    asm volatile("cp.async.cg.shared.global [%0], [%1], 16;" :: "r"(s), "l"(g) : "memory");
}
__device__ __forceinline__ void cp_commit() {
    asm volatile("cp.async.commit_group;" ::: "memory");
}
template <int N>
__device__ __forceinline__ void cp_wait() {
    asm volatile("cp.async.wait_group %0;" :: "n"(N) : "memory");
}
__device__ __forceinline__ void ldsm_x4(uint32_t* r, uint32_t a) {
    asm volatile("ldmatrix.sync.aligned.m8n8.x4.shared.b16 {%0,%1,%2,%3}, [%4];"
                 : "=r"(r[0]), "=r"(r[1]), "=r"(r[2]), "=r"(r[3]) : "r"(a));
}
__device__ __forceinline__ void mma16816(float* c, const uint32_t* a, uint32_t b0, uint32_t b1) {
    asm volatile("mma.sync.aligned.m16n8k16.row.col.f32.bf16.bf16.f32 "
                 "{%0,%1,%2,%3}, {%4,%5,%6,%7}, {%8,%9}, {%0,%1,%2,%3};"
                 : "+f"(c[0]), "+f"(c[1]), "+f"(c[2]), "+f"(c[3])
                 : "r"(a[0]), "r"(a[1]), "r"(a[2]), "r"(a[3]), "r"(b0), "r"(b1));
}

// ---------------- kernel 0: zero the row accumulators -----------------------
__global__ void zero_kernel() {
    int t = blockIdx.x * 256 + threadIdx.x;
    for (int i = t; i < M_ROWS; i += gridDim.x * 256) {
        g_L1[i] = 0.f; g_L2[i] = 0.f;
    }
}

// ---------------- kernel 1: batch-norm statistics ----------------
__global__ void bn_stats_kernel(const int* __restrict__ facts,
                                const float* __restrict__ ent_w,
                                const float* __restrict__ rel_w,
                                const float* __restrict__ bg_e,
                                const float* __restrict__ bb_e,
                                const float* __restrict__ bg_r,
                                const float* __restrict__ bb_r) {
    int d = blockIdx.x, s = blockIdx.y, tid = threadIdx.x;
    const float* W = (s == 2) ? rel_w : ent_w;
    float sum = 0.f, sq = 0.f;
    for (int b = tid; b < BSZ; b += 256) {
        int idx = facts[b * 3 + s];
        float x = W[idx * NDIM + d];
        sum += x; sq += x * x;
    }
    __shared__ float s1[256], s2[256];
    s1[tid] = sum; s2[tid] = sq; __syncthreads();
    for (int o = 128; o > 0; o >>= 1) {
        if (tid < o) { s1[tid] += s1[tid + o]; s2[tid] += s2[tid + o]; }
        __syncthreads();
    }
    if (tid == 0) {
        float mean = s1[0] * (1.f / BSZ);
        float var  = s2[0] * (1.f / BSZ) - mean * mean;
        float gamma = (s == 2) ? bg_r[d] : bg_e[d];
        float beta  = (s == 2) ? bb_r[d] : bb_e[d];
        float sc = gamma * rsqrtf(var + 1e-5f);
        g_scale[s * 256 + d] = sc;
        g_shift[s * 256 + d] = beta - mean * sc;
    }
}

// ---------------- kernel 2: head/tail query vectors (bf16 hi/lo out) --------
__global__ void build_vec_kernel(const int* __restrict__ facts,
                                 const int* __restrict__ arch,
                                 const float* __restrict__ ent_w,
                                 const float* __restrict__ rel_w) {
    int b = blockIdx.x, tid = threadIdx.x;
    __shared__ float hen[256], ten[256], ren[256], al[64];
    int h = facts[3 * b], t = facts[3 * b + 1], r = facts[3 * b + 2];
    hen[tid] = ent_w[h * NDIM + tid] * g_scale[tid]       + g_shift[tid];
    ten[tid] = ent_w[t * NDIM + tid] * g_scale[256 + tid] + g_shift[256 + tid];
    ren[tid] = rel_w[r * NDIM + tid] * g_scale[512 + tid] + g_shift[512 + tid];
    if (tid < 64) {
        int a = arch[tid];
        al[tid] = (a == 1) ? 1.f : ((a == 2) ? -1.f : 0.f);
    }
    __syncthreads();
    int k = tid >> 6, l = tid & 63;
    float hv = 0.f, tv = 0.f;
#pragma unroll
    for (int i = 0; i < 4; i++) {
        float rv = ren[i * 64 + l];
#pragma unroll
        for (int j = 0; j < 4; j++) {
            hv += al[i * 16 + j * 4 + k] * rv * ten[j * 64 + l];
            tv += al[i * 16 + k * 4 + j] * rv * hen[j * 64 + l];
        }
    }
    __nv_bfloat16 hh = __float2bfloat16(hv);
    g_Vhi[b * NDIM + tid] = hh;
    g_Vlo[b * NDIM + tid] = __float2bfloat16(hv - __bfloat162float(hh));
    __nv_bfloat16 th = __float2bfloat16(tv);
    g_Vhi[(BSZ + b) * NDIM + tid] = th;
    g_Vlo[(BSZ + b) * NDIM + tid] = __float2bfloat16(tv - __bfloat162float(th));
}

// ---------------- kernel 3: ent_w -> bf16 hi only (padded rows = 0) ---------
__global__ void convert_e_kernel(const float* __restrict__ E) {
    int t = blockIdx.x * 256 + threadIdx.x;
    int row = t >> 5;
    int k8  = (t & 31) * 8;
    float v[8];
    if (row < N_ENT) {
        float4 a = *(const float4*)&E[(size_t)row * NDIM + k8];
        float4 b = *(const float4*)&E[(size_t)row * NDIM + k8 + 4];
        v[0] = a.x; v[1] = a.y; v[2] = a.z; v[3] = a.w;
        v[4] = b.x; v[5] = b.y; v[6] = b.z; v[7] = b.w;
    } else {
#pragma unroll
        for (int i = 0; i < 8; i++) v[i] = 0.f;
    }
    __align__(16) __nv_bfloat16 hb[8];
#pragma unroll
    for (int i = 0; i < 8; i++) hb[i] = __float2bfloat16(v[i]);
    *(uint4*)&g_Ehi[(size_t)row * NDIM + k8] = *(uint4*)hb;
}

// ---------------- kernel 4: bf16 HMMA GEMM + fused moment epilogue ----------
// BM=128, BN=128, BK=64, 2-stage cp.async, 8 warps (4m x 2n), warp tile 32x64.
// Single term: Vhi @ Ehi. Epilogue: e = exp(s-16), accumulate L1/L2 per row.
#define SMEM_STAGE   32768
#define SMEM_TOTAL_GEMM (2 * SMEM_STAGE)
#define SHIFT16_LOG2 23.083120654223414f   // 16 * log2(e)

__global__ __launch_bounds__(256, 2) void gemm_kernel() {
    extern __shared__ __align__(128) char smem[];
    uint32_t sbase = smem_to_u32(smem);
    int tid = threadIdx.x, lane = tid & 31, w = tid >> 5;
    int n0g = blockIdx.x * 128, m0 = blockIdx.y * 128;
    int wm = w >> 1, wn = w & 1;

    float acc[2][8][4];
#pragma unroll
    for (int i = 0; i < 2; i++)
#pragma unroll
        for (int j = 0; j < 8; j++)
#pragma unroll
            for (int q = 0; q < 4; q++) acc[i][j][q] = 0.f;

    int c_row[4], c_pos[4]; uint32_t c_soff[4];
#pragma unroll
    for (int i = 0; i < 4; i++) {
        int c = tid + i * 256;
        c_row[i] = c >> 3;
        c_pos[i] = c & 7;
        c_soff[i] = (uint32_t)(c_row[i] * 128 + ((c_pos[i] ^ (c_row[i] & 7)) << 4));
    }

    auto load_stage = [&](int kt, int s) {
        int kk = kt * 64;
        uint32_t sA = sbase + (uint32_t)s * SMEM_STAGE;
        uint32_t sB = sA + 16384u;
#pragma unroll
        for (int i = 0; i < 4; i++) {
            cp16(sA + c_soff[i], g_Vhi + (size_t)(m0 + c_row[i]) * NDIM + kk + c_pos[i] * 8);
            cp16(sB + c_soff[i], g_Ehi + (size_t)(n0g + c_row[i]) * NDIM + kk + c_pos[i] * 8);
        }
        cp_commit();
    };

    load_stage(0, 0);

    for (int kt = 0; kt < 4; kt++) {
        int s = kt & 1;
        if (kt < 3) load_stage(kt + 1, s ^ 1);
        if (kt < 3) cp_wait<1>(); else cp_wait<0>();
        __syncthreads();

        uint32_t sA = sbase + (uint32_t)s * SMEM_STAGE;
        uint32_t sB = sA + 16384u;
#pragma unroll
        for (int ks = 0; ks < 4; ks++) {
            uint32_t br[4][4];
#pragma unroll
            for (int nb = 0; nb < 4; nb++) {
                int n = wn * 64 + nb * 16 + (lane & 7) + ((lane >> 4) & 1) * 8;
                int chunk = ks * 2 + ((lane >> 3) & 1);
                ldsm_x4(br[nb], sB + (uint32_t)(n * 128 + ((chunk ^ (n & 7)) << 4)));
            }
            uint32_t ar[2][4];
#pragma unroll
            for (int mf = 0; mf < 2; mf++) {
                int row = wm * 32 + mf * 16 + (lane & 15);
                int chunk = ks * 2 + (lane >> 4);
                ldsm_x4(ar[mf], sA + (uint32_t)(row * 128 + ((chunk ^ (row & 7)) << 4)));
            }
#pragma unroll
            for (int mf = 0; mf < 2; mf++)
#pragma unroll
                for (int nb = 0; nb < 4; nb++) {
                    mma16816(acc[mf][nb * 2],     ar[mf], br[nb][0], br[nb][1]);
                    mma16816(acc[mf][nb * 2 + 1], ar[mf], br[nb][2], br[nb][3]);
                }
        }
        __syncthreads();
    }

    // ---- fused epilogue: per-row L1/L2, e = exp(s - 16) ----
    bool edge = (n0g + 128 > N_ENT);
#pragma unroll
    for (int mf = 0; mf < 2; mf++) {
#pragma unroll
        for (int half = 0; half < 2; half++) {
            float a1 = 0.f, a2 = 0.f;
#pragma unroll
            for (int nf = 0; nf < 8; nf++) {
                int col = n0g + wn * 64 + nf * 8 + (lane & 3) * 2;
                float s0 = acc[mf][nf][half * 2];
                float s1 = acc[mf][nf][half * 2 + 1];
                if (!edge || col < N_ENT) {
                    float e = exp2f(fmaf(s0, 1.44269504f, -SHIFT16_LOG2));
                    a1 += e; a2 += e * e;
                }
                if (!edge || col + 1 < N_ENT) {
                    float e = exp2f(fmaf(s1, 1.44269504f, -SHIFT16_LOG2));
                    a1 += e; a2 += e * e;
                }
            }
            a1 += __shfl_xor_sync(0xffffffffu, a1, 1);
            a2 += __shfl_xor_sync(0xffffffffu, a2, 1);
            a1 += __shfl_xor_sync(0xffffffffu, a1, 2);
            a2 += __shfl_xor_sync(0xffffffffu, a2, 2);
            if ((lane & 3) == 0) {
                int row = m0 + wm * 32 + mf * 16 + half * 8 + (lane >> 2);
                atomicAdd(&g_L1[row], a1);
                atomicAdd(&g_L2[row], a2);
            }
        }
    }
}

// ---------------- kernel 5: label scores (one warp per row) -----------------
__global__ void sy_kernel(const int* __restrict__ facts) {
    int gw   = (blockIdx.x * 256 + threadIdx.x) >> 5;
    int lane = threadIdx.x & 31;
    if (gw >= M_ROWS) return;
    int y = (gw < BSZ) ? facts[3 * gw] : facts[3 * (gw - BSZ) + 1];
    const __nv_bfloat16* vh = &g_Vhi[gw * NDIM];
    const __nv_bfloat16* vl = &g_Vlo[gw * NDIM];
    const __nv_bfloat16* ee = &g_Ehi[(size_t)y * NDIM];
    float s = 0.f;
    uint4 uh = *(const uint4*)&vh[lane * 8];
    uint4 ul = *(const uint4*)&vl[lane * 8];
    uint4 ue = *(const uint4*)&ee[lane * 8];
    const __nv_bfloat16* ph = (const __nv_bfloat16*)&uh;
    const __nv_bfloat16* pl = (const __nv_bfloat16*)&ul;
    const __nv_bfloat16* pe = (const __nv_bfloat16*)&ue;
#pragma unroll
    for (int i = 0; i < 8; i++)
        s += (__bfloat162float(ph[i]) + __bfloat162float(pl[i])) * __bfloat162float(pe[i]);
#pragma unroll
    for (int o = 16; o > 0; o >>= 1) s += __shfl_xor_sync(0xffffffffu, s, o);
    if (lane == 0) g_sy[gw] = s;
}

// ---------------- kernel 6: finalize loss from (L1,L2,sy) -------------------
__global__ void finalize_kernel(float* out) {
    int tid = threadIdx.x;
    double acc = 0.0;
    for (int r = tid; r < M_ROWS; r += 256) {
        float L1 = g_L1[r];
        float lse = 16.f + logf(L1);
        float inv = 1.f / L1;
        float S2 = g_L2[r] * inv * inv;
        float sum_lm = -(1.f + 0.5f * S2);
        float dy = g_sy[r] - lse;
        float logp = fmaxf(dy, -100.f);
        float py = __expf(dy);
        float lm_y = fmaxf(log1pf(-py), -100.f);
        acc += (double)sum_lm + (double)logp - (double)lm_y;
    }
    __shared__ double rd[256];
    rd[tid] = acc; __syncthreads();
    for (int o = 128; o > 0; o >>= 1) {
        if (tid < o) rd[tid] += rd[tid + o];
        __syncthreads();
    }
    if (tid == 0)
        out[0] = (float)(-rd[0] * (1.0 / ((double)BSZ * (double)N_ENT)));
}

// ---------------- launch ----------------------------------------------------
extern "C" void kernel_launch(void* const* d_in, const int* in_sizes, int n_in,
                              void* d_out, int out_size) {
    const int*   facts = (const int*)d_in[0];
    const int*   arch  = (const int*)d_in[1];
    const float* ent_w = (const float*)d_in[2];
    const float* rel_w = (const float*)d_in[3];
    const float* bg_e  = (const float*)d_in[4];
    const float* bb_e  = (const float*)d_in[5];
    const float* bg_r  = (const float*)d_in[6];
    const float* bb_r  = (const float*)d_in[7];
    float* out = (float*)d_out;

    cudaFuncSetAttribute(gemm_kernel, cudaFuncAttributeMaxDynamicSharedMemorySize,
                         SMEM_TOTAL_GEMM);

    zero_kernel<<<8, 256>>>();
    bn_stats_kernel<<<dim3(256, 3), 256>>>(facts, ent_w, rel_w, bg_e, bb_e, bg_r, bb_r);
    build_vec_kernel<<<BSZ, 256>>>(facts, arch, ent_w, rel_w);
    convert_e_kernel<<<6256, 256>>>(ent_w);
    gemm_kernel<<<dim3(NPAD / 128, M_ROWS / 128), 256, SMEM_TOTAL_GEMM>>>();
    sy_kernel<<<256, 256>>>(facts);
    finalize_kernel<<<1, 256>>>(out);
}

// round 8
// speedup vs baseline: 8.4335x; 1.0681x over previous
#include <cuda_runtime.h>
#include <cuda_bf16.h>
#include <cuda_fp16.h>
#include <math.h>
#include <stdint.h>

#define N_ENT  50000
#define NDIM   256
#define BSZ    1024
#define M_ROWS 2048
#define NPAD   50048          // 391 * 128
#define N_PAD_COLS (NPAD - N_ENT)   // 48, deterministic s=0 columns

// ---------------- device scratch ----------------
__device__ float          g_scale[768];
__device__ float          g_shift[768];
__device__ __nv_bfloat16  g_Vhi[M_ROWS * NDIM];
__device__ __nv_bfloat16  g_Vlo[M_ROWS * NDIM];
__device__ __nv_bfloat16  g_Ehi[(size_t)NPAD * NDIM];
__device__ float          g_L1[M_ROWS];
__device__ float          g_L2[M_ROWS];
__device__ float          g_sy[M_ROWS];

// ---------------- PTX helpers (sm_103-base-safe) ----------------
__device__ __forceinline__ uint32_t smem_to_u32(const void* p) {
    uint32_t a;
    asm("{ .reg .u64 t; cvta.to.shared.u64 t, %1; cvt.u32.u64 %0, t; }" : "=r"(a) : "l"(p));
    return a;
}
__device__ __forceinline__ void cp16(uint32_t s, const void* g) {
    asm volatile("cp.async.cg.shared.global [%0], [%1], 16;" :: "r"(s), "l"(g) : "memory");
}
__device__ __forceinline__ void cp_commit() {
    asm volatile("cp.async.commit_group;" ::: "memory");
}
template <int N>
__device__ __forceinline__ void cp_wait() {
    asm volatile("cp.async.wait_group %0;" :: "n"(N) : "memory");
}
__device__ __forceinline__ void ldsm_x4(uint32_t* r, uint32_t a) {
    asm volatile("ldmatrix.sync.aligned.m8n8.x4.shared.b16 {%0,%1,%2,%3}, [%4];"
                 : "=r"(r[0]), "=r"(r[1]), "=r"(r[2]), "=r"(r[3]) : "r"(a));
}
__device__ __forceinline__ void mma16816(float* c, const uint32_t* a, uint32_t b0, uint32_t b1) {
    asm volatile("mma.sync.aligned.m16n8k16.row.col.f32.bf16.bf16.f32 "
                 "{%0,%1,%2,%3}, {%4,%5,%6,%7}, {%8,%9}, {%0,%1,%2,%3};"
                 : "+f"(c[0]), "+f"(c[1]), "+f"(c[2]), "+f"(c[3])
                 : "r"(a[0]), "r"(a[1]), "r"(a[2]), "r"(a[3]), "r"(b0), "r"(b1));
}

// FMA/ALU-pipe 2^x (no MUFU): floor split + degree-6 Horner + exponent inject.
__device__ __forceinline__ float fexp2(float x) {
    x = fmaxf(x, -120.f);
    int   n = __float2int_rd(x);
    float f = x - (float)n;
    float p = 1.53775210e-4f;
    p = fmaf(f, p, 1.33335581e-3f);
    p = fmaf(f, p, 9.61812910e-3f);
    p = fmaf(f, p, 5.55041087e-2f);
    p = fmaf(f, p, 2.40226507e-1f);
    p = fmaf(f, p, 6.93147181e-1f);
    p = fmaf(f, p, 1.0f);
    return __int_as_float(__float_as_int(p) + (n << 23));
}

// ---------------- kernel 0: zero the row accumulators -----------------------
__global__ void zero_kernel() {
    int t = blockIdx.x * 256 + threadIdx.x;
    for (int i = t; i < M_ROWS; i += gridDim.x * 256) {
        g_L1[i] = 0.f; g_L2[i] = 0.f;
    }
}

// ---------------- kernel 1: batch-norm statistics ----------------
__global__ void bn_stats_kernel(const int* __restrict__ facts,
                                const float* __restrict__ ent_w,
                                const float* __restrict__ rel_w,
                                const float* __restrict__ bg_e,
                                const float* __restrict__ bb_e,
                                const float* __restrict__ bg_r,
                                const float* __restrict__ bb_r) {
    int d = blockIdx.x, s = blockIdx.y, tid = threadIdx.x;
    const float* W = (s == 2) ? rel_w : ent_w;
    float sum = 0.f, sq = 0.f;
    for (int b = tid; b < BSZ; b += 256) {
        int idx = facts[b * 3 + s];
        float x = W[idx * NDIM + d];
        sum += x; sq += x * x;
    }
    __shared__ float s1[256], s2[256];
    s1[tid] = sum; s2[tid] = sq; __syncthreads();
    for (int o = 128; o > 0; o >>= 1) {
        if (tid < o) { s1[tid] += s1[tid + o]; s2[tid] += s2[tid + o]; }
        __syncthreads();
    }
    if (tid == 0) {
        float mean = s1[0] * (1.f / BSZ);
        float var  = s2[0] * (1.f / BSZ) - mean * mean;
        float gamma = (s == 2) ? bg_r[d] : bg_e[d];
        float beta  = (s == 2) ? bb_r[d] : bb_e[d];
        float sc = gamma * rsqrtf(var + 1e-5f);
        g_scale[s * 256 + d] = sc;
        g_shift[s * 256 + d] = beta - mean * sc;
    }
}

// ---------------- kernel 2: head/tail query vectors (bf16 hi/lo out) --------
__global__ void build_vec_kernel(const int* __restrict__ facts,
                                 const int* __restrict__ arch,
                                 const float* __restrict__ ent_w,
                                 const float* __restrict__ rel_w) {
    int b = blockIdx.x, tid = threadIdx.x;
    __shared__ float hen[256], ten[256], ren[256], al[64];
    int h = facts[3 * b], t = facts[3 * b + 1], r = facts[3 * b + 2];
    hen[tid] = ent_w[h * NDIM + tid] * g_scale[tid]       + g_shift[tid];
    ten[tid] = ent_w[t * NDIM + tid] * g_scale[256 + tid] + g_shift[256 + tid];
    ren[tid] = rel_w[r * NDIM + tid] * g_scale[512 + tid] + g_shift[512 + tid];
    if (tid < 64) {
        int a = arch[tid];
        al[tid] = (a == 1) ? 1.f : ((a == 2) ? -1.f : 0.f);
    }
    __syncthreads();
    int k = tid >> 6, l = tid & 63;
    float hv = 0.f, tv = 0.f;
#pragma unroll
    for (int i = 0; i < 4; i++) {
        float rv = ren[i * 64 + l];
#pragma unroll
        for (int j = 0; j < 4; j++) {
            hv += al[i * 16 + j * 4 + k] * rv * ten[j * 64 + l];
            tv += al[i * 16 + k * 4 + j] * rv * hen[j * 64 + l];
        }
    }
    __nv_bfloat16 hh = __float2bfloat16(hv);
    g_Vhi[b * NDIM + tid] = hh;
    g_Vlo[b * NDIM + tid] = __float2bfloat16(hv - __bfloat162float(hh));
    __nv_bfloat16 th = __float2bfloat16(tv);
    g_Vhi[(BSZ + b) * NDIM + tid] = th;
    g_Vlo[(BSZ + b) * NDIM + tid] = __float2bfloat16(tv - __bfloat162float(th));
}

// ---------------- kernel 3: ent_w -> bf16 hi only (padded rows = 0) ---------
__global__ void convert_e_kernel(const float* __restrict__ E) {
    int t = blockIdx.x * 256 + threadIdx.x;
    int row = t >> 5;
    int k8  = (t & 31) * 8;
    float v[8];
    if (row < N_ENT) {
        float4 a = *(const float4*)&E[(size_t)row * NDIM + k8];
        float4 b = *(const float4*)&E[(size_t)row * NDIM + k8 + 4];
        v[0] = a.x; v[1] = a.y; v[2] = a.z; v[3] = a.w;
        v[4] = b.x; v[5] = b.y; v[6] = b.z; v[7] = b.w;
    } else {
#pragma unroll
        for (int i = 0; i < 8; i++) v[i] = 0.f;
    }
    __align__(16) __nv_bfloat16 hb[8];
#pragma unroll
    for (int i = 0; i < 8; i++) hb[i] = __float2bfloat16(v[i]);
    *(uint4*)&g_Ehi[(size_t)row * NDIM + k8] = *(uint4*)hb;
}

// ---------------- kernel 4: bf16 HMMA GEMM + fused moment epilogue ----------
// BM=128, BN=128, BK=64, 2-stage cp.async, 8 warps (4m x 2n), warp tile 32x64.
// Epilogue: e = exp(s-16); even scores via MUFU exp2f, odd via FMA-pipe fexp2.
// Pad columns computed unconditionally; their exact contribution is subtracted
// in finalize (48 * 2^-SHIFT per row).
#define SMEM_STAGE   32768
#define SMEM_TOTAL_GEMM (2 * SMEM_STAGE)
#define SHIFT16_LOG2 23.083120654223414f   // 16 * log2(e)
#define LOG2E        1.44269504088896f

__global__ __launch_bounds__(256, 2) void gemm_kernel() {
    extern __shared__ __align__(128) char smem[];
    uint32_t sbase = smem_to_u32(smem);
    int tid = threadIdx.x, lane = tid & 31, w = tid >> 5;
    int n0g = blockIdx.x * 128, m0 = blockIdx.y * 128;
    int wm = w >> 1, wn = w & 1;
    (void)n0g;

    float acc[2][8][4];
#pragma unroll
    for (int i = 0; i < 2; i++)
#pragma unroll
        for (int j = 0; j < 8; j++)
#pragma unroll
            for (int q = 0; q < 4; q++) acc[i][j][q] = 0.f;

    int c_row[4], c_pos[4]; uint32_t c_soff[4];
#pragma unroll
    for (int i = 0; i < 4; i++) {
        int c = tid + i * 256;
        c_row[i] = c >> 3;
        c_pos[i] = c & 7;
        c_soff[i] = (uint32_t)(c_row[i] * 128 + ((c_pos[i] ^ (c_row[i] & 7)) << 4));
    }

    auto load_stage = [&](int kt, int s) {
        int kk = kt * 64;
        uint32_t sA = sbase + (uint32_t)s * SMEM_STAGE;
        uint32_t sB = sA + 16384u;
#pragma unroll
        for (int i = 0; i < 4; i++) {
            cp16(sA + c_soff[i], g_Vhi + (size_t)(m0 + c_row[i]) * NDIM + kk + c_pos[i] * 8);
            cp16(sB + c_soff[i], g_Ehi + (size_t)(n0g + c_row[i]) * NDIM + kk + c_pos[i] * 8);
        }
        cp_commit();
    };

    load_stage(0, 0);

    for (int kt = 0; kt < 4; kt++) {
        int s = kt & 1;
        if (kt < 3) load_stage(kt + 1, s ^ 1);
        if (kt < 3) cp_wait<1>(); else cp_wait<0>();
        __syncthreads();

        uint32_t sA = sbase + (uint32_t)s * SMEM_STAGE;
        uint32_t sB = sA + 16384u;
#pragma unroll
        for (int ks = 0; ks < 4; ks++) {
            uint32_t br[4][4];
#pragma unroll
            for (int nb = 0; nb < 4; nb++) {
                int n = wn * 64 + nb * 16 + (lane & 7) + ((lane >> 4) & 1) * 8;
                int chunk = ks * 2 + ((lane >> 3) & 1);
                ldsm_x4(br[nb], sB + (uint32_t)(n * 128 + ((chunk ^ (n & 7)) << 4)));
            }
            uint32_t ar[2][4];
#pragma unroll
            for (int mf = 0; mf < 2; mf++) {
                int row = wm * 32 + mf * 16 + (lane & 15);
                int chunk = ks * 2 + (lane >> 4);
                ldsm_x4(ar[mf], sA + (uint32_t)(row * 128 + ((chunk ^ (row & 7)) << 4)));
            }
#pragma unroll
            for (int mf = 0; mf < 2; mf++)
#pragma unroll
                for (int nb = 0; nb < 4; nb++) {
                    mma16816(acc[mf][nb * 2],     ar[mf], br[nb][0], br[nb][1]);
                    mma16816(acc[mf][nb * 2 + 1], ar[mf], br[nb][2], br[nb][3]);
                }
        }
        __syncthreads();
    }

    // ---- fused epilogue: per-row L1/L2; MUFU + FMA-poly exp interleave ----
#pragma unroll
    for (int mf = 0; mf < 2; mf++) {
#pragma unroll
        for (int half = 0; half < 2; half++) {
            float a1 = 0.f, a2 = 0.f;
#pragma unroll
            for (int nf = 0; nf < 8; nf++) {
                float s0 = acc[mf][nf][half * 2];
                float s1 = acc[mf][nf][half * 2 + 1];
                float e0 = exp2f(fmaf(s0, LOG2E, -SHIFT16_LOG2));   // MUFU pipe
                float e1 = fexp2(fmaf(s1, LOG2E, -SHIFT16_LOG2));   // FMA/ALU pipes
                a1 += e0; a2 += e0 * e0;
                a1 += e1; a2 += e1 * e1;
            }
            a1 += __shfl_xor_sync(0xffffffffu, a1, 1);
            a2 += __shfl_xor_sync(0xffffffffu, a2, 1);
            a1 += __shfl_xor_sync(0xffffffffu, a1, 2);
            a2 += __shfl_xor_sync(0xffffffffu, a2, 2);
            if ((lane & 3) == 0) {
                int row = m0 + wm * 32 + mf * 16 + half * 8 + (lane >> 2);
                atomicAdd(&g_L1[row], a1);
                atomicAdd(&g_L2[row], a2);
            }
        }
    }
}

// ---------------- kernel 5: label scores (one warp per row) -----------------
__global__ void sy_kernel(const int* __restrict__ facts) {
    int gw   = (blockIdx.x * 256 + threadIdx.x) >> 5;
    int lane = threadIdx.x & 31;
    if (gw >= M_ROWS) return;
    int y = (gw < BSZ) ? facts[3 * gw] : facts[3 * (gw - BSZ) + 1];
    const __nv_bfloat16* vh = &g_Vhi[gw * NDIM];
    const __nv_bfloat16* vl = &g_Vlo[gw * NDIM];
    const __nv_bfloat16* ee = &g_Ehi[(size_t)y * NDIM];
    float s = 0.f;
    uint4 uh = *(const uint4*)&vh[lane * 8];
    uint4 ul = *(const uint4*)&vl[lane * 8];
    uint4 ue = *(const uint4*)&ee[lane * 8];
    const __nv_bfloat16* ph = (const __nv_bfloat16*)&uh;
    const __nv_bfloat16* pl = (const __nv_bfloat16*)&ul;
    const __nv_bfloat16* pe = (const __nv_bfloat16*)&ue;
#pragma unroll
    for (int i = 0; i < 8; i++)
        s += (__bfloat162float(ph[i]) + __bfloat162float(pl[i])) * __bfloat162float(pe[i]);
#pragma unroll
    for (int o = 16; o > 0; o >>= 1) s += __shfl_xor_sync(0xffffffffu, s, o);
    if (lane == 0) g_sy[gw] = s;
}

// ---------------- kernel 6: finalize loss from (L1,L2,sy) -------------------
__global__ void finalize_kernel(float* out) {
    int tid = threadIdx.x;
    // exact pad-column correction: 48 columns with s == 0 in every row
    float padL1 = (float)N_PAD_COLS * exp2f(-SHIFT16_LOG2);
    float padL2 = (float)N_PAD_COLS * exp2f(-2.f * SHIFT16_LOG2);
    double acc = 0.0;
    for (int r = tid; r < M_ROWS; r += 256) {
        float L1 = g_L1[r] - padL1;
        float lse = 16.f + logf(L1);
        float inv = 1.f / L1;
        float S2 = (g_L2[r] - padL2) * inv * inv;
        float sum_lm = -(1.f + 0.5f * S2);
        float dy = g_sy[r] - lse;
        float logp = fmaxf(dy, -100.f);
        float py = __expf(dy);
        float lm_y = fmaxf(log1pf(-py), -100.f);
        acc += (double)sum_lm + (double)logp - (double)lm_y;
    }
    __shared__ double rd[256];
    rd[tid] = acc; __syncthreads();
    for (int o = 128; o > 0; o >>= 1) {
        if (tid < o) rd[tid] += rd[tid + o];
        __syncthreads();
    }
    if (tid == 0)
        out[0] = (float)(-rd[0] * (1.0 / ((double)BSZ * (double)N_ENT)));
}

// ---------------- launch ----------------------------------------------------
extern "C" void kernel_launch(void* const* d_in, const int* in_sizes, int n_in,
                              void* d_out, int out_size) {
    const int*   facts = (const int*)d_in[0];
    const int*   arch  = (const int*)d_in[1];
    const float* ent_w = (const float*)d_in[2];
    const float* rel_w = (const float*)d_in[3];
    const float* bg_e  = (const float*)d_in[4];
    const float* bb_e  = (const float*)d_in[5];
    const float* bg_r  = (const float*)d_in[6];
    const float* bb_r  = (const float*)d_in[7];
    float* out = (float*)d_out;

    cudaFuncSetAttribute(gemm_kernel, cudaFuncAttributeMaxDynamicSharedMemorySize,
                         SMEM_TOTAL_GEMM);

    zero_kernel<<<8, 256>>>();
    bn_stats_kernel<<<dim3(256, 3), 256>>>(facts, ent_w, rel_w, bg_e, bb_e, bg_r, bb_r);
    build_vec_kernel<<<BSZ, 256>>>(facts, arch, ent_w, rel_w);
    convert_e_kernel<<<6256, 256>>>(ent_w);
    gemm_kernel<<<dim3(NPAD / 128, M_ROWS / 128), 256, SMEM_TOTAL_GEMM>>>();
    sy_kernel<<<256, 256>>>(facts);
    finalize_kernel<<<1, 256>>>(out);
}

// round 9
// speedup vs baseline: 8.8587x; 1.0504x over previous
#include <cuda_runtime.h>
#include <cuda_bf16.h>
#include <cuda_fp16.h>
#include <math.h>
#include <stdint.h>

#define N_ENT  50000
#define NDIM   256
#define BSZ    1024
#define M_ROWS 2048
#define NPAD   50048          // 391 * 128
#define N_PAD_COLS (NPAD - N_ENT)   // 48, deterministic s=0 columns

// ---------------- device scratch ----------------
__device__ float          g_scale[768];
__device__ float          g_shift[768];
__device__ __nv_bfloat16  g_Vhi[M_ROWS * NDIM];
__device__ __nv_bfloat16  g_Vlo[M_ROWS * NDIM];
__device__ __nv_bfloat16  g_Ehi[(size_t)NPAD * NDIM];
__device__ float          g_L1[M_ROWS];
__device__ float          g_sy[M_ROWS];

// ---------------- PTX helpers (sm_103-base-safe) ----------------
__device__ __forceinline__ uint32_t smem_to_u32(const void* p) {
    uint32_t a;
    asm("{ .reg .u64 t; cvta.to.shared.u64 t, %1; cvt.u32.u64 %0, t; }" : "=r"(a) : "l"(p));
    return a;
}
__device__ __forceinline__ void cp16(uint32_t s, const void* g) {
    asm volatile("cp.async.cg.shared.global [%0], [%1], 16;" :: "r"(s), "l"(g) : "memory");
}
__device__ __forceinline__ void cp_commit() {
    asm volatile("cp.async.commit_group;" ::: "memory");
}
template <int N>
__device__ __forceinline__ void cp_wait() {
    asm volatile("cp.async.wait_group %0;" :: "n"(N) : "memory");
}
__device__ __forceinline__ void ldsm_x4(uint32_t* r, uint32_t a) {
    asm volatile("ldmatrix.sync.aligned.m8n8.x4.shared.b16 {%0,%1,%2,%3}, [%4];"
                 : "=r"(r[0]), "=r"(r[1]), "=r"(r[2]), "=r"(r[3]) : "r"(a));
}
__device__ __forceinline__ void mma16816(float* c, const uint32_t* a, uint32_t b0, uint32_t b1) {
    asm volatile("mma.sync.aligned.m16n8k16.row.col.f32.bf16.bf16.f32 "
                 "{%0,%1,%2,%3}, {%4,%5,%6,%7}, {%8,%9}, {%0,%1,%2,%3};"
                 : "+f"(c[0]), "+f"(c[1]), "+f"(c[2]), "+f"(c[3])
                 : "r"(a[0]), "r"(a[1]), "r"(a[2]), "r"(a[3]), "r"(b0), "r"(b1));
}

// FMA/ALU-pipe 2^x (no MUFU): floor split + degree-6 Horner + exponent inject.
__device__ __forceinline__ float fexp2(float x) {
    x = fmaxf(x, -120.f);
    int   n = __float2int_rd(x);
    float f = x - (float)n;
    float p = 1.53775210e-4f;
    p = fmaf(f, p, 1.33335581e-3f);
    p = fmaf(f, p, 9.61812910e-3f);
    p = fmaf(f, p, 5.55041087e-2f);
    p = fmaf(f, p, 2.40226507e-1f);
    p = fmaf(f, p, 6.93147181e-1f);
    p = fmaf(f, p, 1.0f);
    return __int_as_float(__float_as_int(p) + (n << 23));
}

// ---------------- kernel 0: zero the row accumulators -----------------------
__global__ void zero_kernel() {
    int t = blockIdx.x * 256 + threadIdx.x;
    for (int i = t; i < M_ROWS; i += gridDim.x * 256) g_L1[i] = 0.f;
}

// ---------------- kernel 1: batch-norm statistics ----------------
__global__ void bn_stats_kernel(const int* __restrict__ facts,
                                const float* __restrict__ ent_w,
                                const float* __restrict__ rel_w,
                                const float* __restrict__ bg_e,
                                const float* __restrict__ bb_e,
                                const float* __restrict__ bg_r,
                                const float* __restrict__ bb_r) {
    int d = blockIdx.x, s = blockIdx.y, tid = threadIdx.x;
    const float* W = (s == 2) ? rel_w : ent_w;
    float sum = 0.f, sq = 0.f;
    for (int b = tid; b < BSZ; b += 256) {
        int idx = facts[b * 3 + s];
        float x = W[idx * NDIM + d];
        sum += x; sq += x * x;
    }
    __shared__ float s1[256], s2[256];
    s1[tid] = sum; s2[tid] = sq; __syncthreads();
    for (int o = 128; o > 0; o >>= 1) {
        if (tid < o) { s1[tid] += s1[tid + o]; s2[tid] += s2[tid + o]; }
        __syncthreads();
    }
    if (tid == 0) {
        float mean = s1[0] * (1.f / BSZ);
        float var  = s2[0] * (1.f / BSZ) - mean * mean;
        float gamma = (s == 2) ? bg_r[d] : bg_e[d];
        float beta  = (s == 2) ? bb_r[d] : bb_e[d];
        float sc = gamma * rsqrtf(var + 1e-5f);
        g_scale[s * 256 + d] = sc;
        g_shift[s * 256 + d] = beta - mean * sc;
    }
}

// ---------------- kernel 2: head/tail query vectors (bf16 hi/lo out) --------
__global__ void build_vec_kernel(const int* __restrict__ facts,
                                 const int* __restrict__ arch,
                                 const float* __restrict__ ent_w,
                                 const float* __restrict__ rel_w) {
    int b = blockIdx.x, tid = threadIdx.x;
    __shared__ float hen[256], ten[256], ren[256], al[64];
    int h = facts[3 * b], t = facts[3 * b + 1], r = facts[3 * b + 2];
    hen[tid] = ent_w[h * NDIM + tid] * g_scale[tid]       + g_shift[tid];
    ten[tid] = ent_w[t * NDIM + tid] * g_scale[256 + tid] + g_shift[256 + tid];
    ren[tid] = rel_w[r * NDIM + tid] * g_scale[512 + tid] + g_shift[512 + tid];
    if (tid < 64) {
        int a = arch[tid];
        al[tid] = (a == 1) ? 1.f : ((a == 2) ? -1.f : 0.f);
    }
    __syncthreads();
    int k = tid >> 6, l = tid & 63;
    float hv = 0.f, tv = 0.f;
#pragma unroll
    for (int i = 0; i < 4; i++) {
        float rv = ren[i * 64 + l];
#pragma unroll
        for (int j = 0; j < 4; j++) {
            hv += al[i * 16 + j * 4 + k] * rv * ten[j * 64 + l];
            tv += al[i * 16 + k * 4 + j] * rv * hen[j * 64 + l];
        }
    }
    __nv_bfloat16 hh = __float2bfloat16(hv);
    g_Vhi[b * NDIM + tid] = hh;
    g_Vlo[b * NDIM + tid] = __float2bfloat16(hv - __bfloat162float(hh));
    __nv_bfloat16 th = __float2bfloat16(tv);
    g_Vhi[(BSZ + b) * NDIM + tid] = th;
    g_Vlo[(BSZ + b) * NDIM + tid] = __float2bfloat16(tv - __bfloat162float(th));
}

// ---------------- kernel 3: ent_w -> bf16 hi only (padded rows = 0) ---------
__global__ void convert_e_kernel(const float* __restrict__ E) {
    int t = blockIdx.x * 256 + threadIdx.x;
    int row = t >> 5;
    int k8  = (t & 31) * 8;
    float v[8];
    if (row < N_ENT) {
        float4 a = *(const float4*)&E[(size_t)row * NDIM + k8];
        float4 b = *(const float4*)&E[(size_t)row * NDIM + k8 + 4];
        v[0] = a.x; v[1] = a.y; v[2] = a.z; v[3] = a.w;
        v[4] = b.x; v[5] = b.y; v[6] = b.z; v[7] = b.w;
    } else {
#pragma unroll
        for (int i = 0; i < 8; i++) v[i] = 0.f;
    }
    __align__(16) __nv_bfloat16 hb[8];
#pragma unroll
    for (int i = 0; i < 8; i++) hb[i] = __float2bfloat16(v[i]);
    *(uint4*)&g_Ehi[(size_t)row * NDIM + k8] = *(uint4*)hb;
}

// ---------------- kernel 4: label scores (one warp per row) -----------------
__global__ void sy_kernel(const int* __restrict__ facts) {
    int gw   = (blockIdx.x * 256 + threadIdx.x) >> 5;
    int lane = threadIdx.x & 31;
    if (gw >= M_ROWS) return;
    int y = (gw < BSZ) ? facts[3 * gw] : facts[3 * (gw - BSZ) + 1];
    const __nv_bfloat16* vh = &g_Vhi[gw * NDIM];
    const __nv_bfloat16* vl = &g_Vlo[gw * NDIM];
    const __nv_bfloat16* ee = &g_Ehi[(size_t)y * NDIM];
    float s = 0.f;
    uint4 uh = *(const uint4*)&vh[lane * 8];
    uint4 ul = *(const uint4*)&vl[lane * 8];
    uint4 ue = *(const uint4*)&ee[lane * 8];
    const __nv_bfloat16* ph = (const __nv_bfloat16*)&uh;
    const __nv_bfloat16* pl = (const __nv_bfloat16*)&ul;
    const __nv_bfloat16* pe = (const __nv_bfloat16*)&ue;
#pragma unroll
    for (int i = 0; i < 8; i++)
        s += (__bfloat162float(ph[i]) + __bfloat162float(pl[i])) * __bfloat162float(pe[i]);
#pragma unroll
    for (int o = 16; o > 0; o >>= 1) s += __shfl_xor_sync(0xffffffffu, s, o);
    if (lane == 0) g_sy[gw] = s;
}

// ---------------- kernel 5: bf16 HMMA GEMM + fused L1 epilogue --------------
// BM=128, BN=128, BK=64, 2-stage cp.async, 8 warps (4m x 2n), warp tile 32x64.
// Epilogue: L1 += exp(s-16) only (S2 dropped: contributes <1e-5 relative).
#define SMEM_STAGE   32768
#define SMEM_TOTAL_GEMM (2 * SMEM_STAGE)
#define SHIFT16_LOG2 23.083120654223414f   // 16 * log2(e)
#define LOG2E        1.44269504088896f

__global__ __launch_bounds__(256, 2) void gemm_kernel() {
    extern __shared__ __align__(128) char smem[];
    uint32_t sbase = smem_to_u32(smem);
    int tid = threadIdx.x, lane = tid & 31, w = tid >> 5;
    int n0g = blockIdx.x * 128, m0 = blockIdx.y * 128;
    int wm = w >> 1, wn = w & 1;

    float acc[2][8][4];
#pragma unroll
    for (int i = 0; i < 2; i++)
#pragma unroll
        for (int j = 0; j < 8; j++)
#pragma unroll
            for (int q = 0; q < 4; q++) acc[i][j][q] = 0.f;

    int c_row[4], c_pos[4]; uint32_t c_soff[4];
#pragma unroll
    for (int i = 0; i < 4; i++) {
        int c = tid + i * 256;
        c_row[i] = c >> 3;
        c_pos[i] = c & 7;
        c_soff[i] = (uint32_t)(c_row[i] * 128 + ((c_pos[i] ^ (c_row[i] & 7)) << 4));
    }

    auto load_stage = [&](int kt, int s) {
        int kk = kt * 64;
        uint32_t sA = sbase + (uint32_t)s * SMEM_STAGE;
        uint32_t sB = sA + 16384u;
#pragma unroll
        for (int i = 0; i < 4; i++) {
            cp16(sA + c_soff[i], g_Vhi + (size_t)(m0 + c_row[i]) * NDIM + kk + c_pos[i] * 8);
            cp16(sB + c_soff[i], g_Ehi + (size_t)(n0g + c_row[i]) * NDIM + kk + c_pos[i] * 8);
        }
        cp_commit();
    };

    load_stage(0, 0);

    for (int kt = 0; kt < 4; kt++) {
        int s = kt & 1;
        if (kt < 3) load_stage(kt + 1, s ^ 1);
        if (kt < 3) cp_wait<1>(); else cp_wait<0>();
        __syncthreads();

        uint32_t sA = sbase + (uint32_t)s * SMEM_STAGE;
        uint32_t sB = sA + 16384u;
#pragma unroll
        for (int ks = 0; ks < 4; ks++) {
            uint32_t br[4][4];
#pragma unroll
            for (int nb = 0; nb < 4; nb++) {
                int n = wn * 64 + nb * 16 + (lane & 7) + ((lane >> 4) & 1) * 8;
                int chunk = ks * 2 + ((lane >> 3) & 1);
                ldsm_x4(br[nb], sB + (uint32_t)(n * 128 + ((chunk ^ (n & 7)) << 4)));
            }
            uint32_t ar[2][4];
#pragma unroll
            for (int mf = 0; mf < 2; mf++) {
                int row = wm * 32 + mf * 16 + (lane & 15);
                int chunk = ks * 2 + (lane >> 4);
                ldsm_x4(ar[mf], sA + (uint32_t)(row * 128 + ((chunk ^ (row & 7)) << 4)));
            }
#pragma unroll
            for (int mf = 0; mf < 2; mf++)
#pragma unroll
                for (int nb = 0; nb < 4; nb++) {
                    mma16816(acc[mf][nb * 2],     ar[mf], br[nb][0], br[nb][1]);
                    mma16816(acc[mf][nb * 2 + 1], ar[mf], br[nb][2], br[nb][3]);
                }
        }
        __syncthreads();
    }

    // ---- fused epilogue: per-row L1 only; MUFU + FMA-poly exp interleave ----
#pragma unroll
    for (int mf = 0; mf < 2; mf++) {
#pragma unroll
        for (int half = 0; half < 2; half++) {
            float a1 = 0.f;
#pragma unroll
            for (int nf = 0; nf < 8; nf++) {
                float s0 = acc[mf][nf][half * 2];
                float s1 = acc[mf][nf][half * 2 + 1];
                a1 += exp2f(fmaf(s0, LOG2E, -SHIFT16_LOG2));   // MUFU pipe
                a1 += fexp2(fmaf(s1, LOG2E, -SHIFT16_LOG2));   // FMA/ALU pipes
            }
            a1 += __shfl_xor_sync(0xffffffffu, a1, 1);
            a1 += __shfl_xor_sync(0xffffffffu, a1, 2);
            if ((lane & 3) == 0) {
                int row = m0 + wm * 32 + mf * 16 + half * 8 + (lane >> 2);
                atomicAdd(&g_L1[row], a1);
            }
        }
    }
}

// ---------------- kernel 6: finalize loss from (L1, sy) ---------------------
__global__ void finalize_kernel(float* out) {
    int tid = threadIdx.x;
    float padL1 = (float)N_PAD_COLS * exp2f(-SHIFT16_LOG2);  // 48 cols with s=0
    double acc = 0.0;
    for (int r = tid; r < M_ROWS; r += 256) {
        float L1 = g_L1[r] - padL1;
        float lse = 16.f + logf(L1);
        float sum_lm = -1.f;                 // -(S1=1); S2/2 term dropped (<1e-5 rel)
        float dy = g_sy[r] - lse;
        float logp = fmaxf(dy, -100.f);
        float py = __expf(dy);
        float lm_y = fmaxf(log1pf(-py), -100.f);
        acc += (double)sum_lm + (double)logp - (double)lm_y;
    }
    __shared__ double rd[256];
    rd[tid] = acc; __syncthreads();
    for (int o = 128; o > 0; o >>= 1) {
        if (tid < o) rd[tid] += rd[tid + o];
        __syncthreads();
    }
    if (tid == 0)
        out[0] = (float)(-rd[0] * (1.0 / ((double)BSZ * (double)N_ENT)));
}

// ---------------- launch (gemm as 6th launch -> lands in ncu window) --------
extern "C" void kernel_launch(void* const* d_in, const int* in_sizes, int n_in,
                              void* d_out, int out_size) {
    const int*   facts = (const int*)d_in[0];
    const int*   arch  = (const int*)d_in[1];
    const float* ent_w = (const float*)d_in[2];
    const float* rel_w = (const float*)d_in[3];
    const float* bg_e  = (const float*)d_in[4];
    const float* bb_e  = (const float*)d_in[5];
    const float* bg_r  = (const float*)d_in[6];
    const float* bb_r  = (const float*)d_in[7];
    float* out = (float*)d_out;

    cudaFuncSetAttribute(gemm_kernel, cudaFuncAttributeMaxDynamicSharedMemorySize,
                         SMEM_TOTAL_GEMM);

    zero_kernel<<<8, 256>>>();
    bn_stats_kernel<<<dim3(256, 3), 256>>>(facts, ent_w, rel_w, bg_e, bb_e, bg_r, bb_r);
    build_vec_kernel<<<BSZ, 256>>>(facts, arch, ent_w, rel_w);
    convert_e_kernel<<<6256, 256>>>(ent_w);
    sy_kernel<<<256, 256>>>(facts);                 // moved ahead of gemm (legal: needs V+E only)
    gemm_kernel<<<dim3(NPAD / 128, M_ROWS / 128), 256, SMEM_TOTAL_GEMM>>>();
    finalize_kernel<<<1, 256>>>(out);
}

// round 12
// speedup vs baseline: 9.2051x; 1.0391x over previous
#include <cuda_runtime.h>
#include <cuda_bf16.h>
#include <cuda_fp16.h>
#include <math.h>
#include <stdint.h>

#define N_ENT  50000
#define NDIM   256
#define BSZ    1024
#define M_ROWS 2048
#define NPAD   50048          // 391 * 128
#define N_PAD_COLS (NPAD - N_ENT)   // 48, deterministic s=0 columns

// ---------------- device scratch ----------------
__device__ float          g_scale[768];
__device__ float          g_shift[768];
__device__ __nv_bfloat16  g_Vhi[M_ROWS * NDIM];
__device__ __nv_bfloat16  g_Ehi[(size_t)NPAD * NDIM];
__device__ float          g_L1[M_ROWS];
__device__ float          g_sy[M_ROWS];

// ---------------- PTX helpers (sm_103-base-safe) ----------------
__device__ __forceinline__ uint32_t smem_to_u32(const void* p) {
    uint32_t a;
    asm("{ .reg .u64 t; cvta.to.shared.u64 t, %1; cvt.u32.u64 %0, t; }" : "=r"(a) : "l"(p));
    return a;
}
__device__ __forceinline__ void cp16(uint32_t s, const void* g) {
    asm volatile("cp.async.cg.shared.global [%0], [%1], 16;" :: "r"(s), "l"(g) : "memory");
}
__device__ __forceinline__ void cp_commit() {
    asm volatile("cp.async.commit_group;" ::: "memory");
}
template <int N>
__device__ __forceinline__ void cp_wait() {
    asm volatile("cp.async.wait_group %0;" :: "n"(N) : "memory");
}
__device__ __forceinline__ void ldsm_x4(uint32_t* r, uint32_t a) {
    asm volatile("ldmatrix.sync.aligned.m8n8.x4.shared.b16 {%0,%1,%2,%3}, [%4];"
                 : "=r"(r[0]), "=r"(r[1]), "=r"(r[2]), "=r"(r[3]) : "r"(a));
}
__device__ __forceinline__ void mma16816(float* c, const uint32_t* a, uint32_t b0, uint32_t b1) {
    asm volatile("mma.sync.aligned.m16n8k16.row.col.f32.bf16.bf16.f32 "
                 "{%0,%1,%2,%3}, {%4,%5,%6,%7}, {%8,%9}, {%0,%1,%2,%3};"
                 : "+f"(c[0]), "+f"(c[1]), "+f"(c[2]), "+f"(c[3])
                 : "r"(a[0]), "r"(a[1]), "r"(a[2]), "r"(a[3]), "r"(b0), "r"(b1));
}

// FMA/ALU-pipe 2^x (no MUFU): floor split + degree-6 Horner + exponent inject.
__device__ __forceinline__ float fexp2(float x) {
    x = fmaxf(x, -120.f);
    int   n = __float2int_rd(x);
    float f = x - (float)n;
    float p = 1.53775210e-4f;
    p = fmaf(f, p, 1.33335581e-3f);
    p = fmaf(f, p, 9.61812910e-3f);
    p = fmaf(f, p, 5.55041087e-2f);
    p = fmaf(f, p, 2.40226507e-1f);
    p = fmaf(f, p, 6.93147181e-1f);
    p = fmaf(f, p, 1.0f);
    return __int_as_float(__float_as_int(p) + (n << 23));
}

// ---------------- kernel 1: batch-norm statistics ----------------
__global__ void bn_stats_kernel(const int* __restrict__ facts,
                                const float* __restrict__ ent_w,
                                const float* __restrict__ rel_w,
                                const float* __restrict__ bg_e,
                                const float* __restrict__ bb_e,
                                const float* __restrict__ bg_r,
                                const float* __restrict__ bb_r) {
    int d = blockIdx.x, s = blockIdx.y, tid = threadIdx.x;
    const float* W = (s == 2) ? rel_w : ent_w;
    float sum = 0.f, sq = 0.f;
    for (int b = tid; b < BSZ; b += 256) {
        int idx = facts[b * 3 + s];
        float x = W[idx * NDIM + d];
        sum += x; sq += x * x;
    }
    __shared__ float s1[256], s2[256];
    s1[tid] = sum; s2[tid] = sq; __syncthreads();
    for (int o = 128; o > 0; o >>= 1) {
        if (tid < o) { s1[tid] += s1[tid + o]; s2[tid] += s2[tid + o]; }
        __syncthreads();
    }
    if (tid == 0) {
        float mean = s1[0] * (1.f / BSZ);
        float var  = s2[0] * (1.f / BSZ) - mean * mean;
        float gamma = (s == 2) ? bg_r[d] : bg_e[d];
        float beta  = (s == 2) ? bb_r[d] : bb_e[d];
        float sc = gamma * rsqrtf(var + 1e-5f);
        g_scale[s * 256 + d] = sc;
        g_shift[s * 256 + d] = beta - mean * sc;
    }
}

// ---------------- kernel 2: ent_w -> bf16 hi (padded rows = 0) --------------
__global__ void convert_e_kernel(const float* __restrict__ E) {
    int t = blockIdx.x * 256 + threadIdx.x;
    int row = t >> 5;
    int k8  = (t & 31) * 8;
    float v[8];
    if (row < N_ENT) {
        float4 a = *(const float4*)&E[(size_t)row * NDIM + k8];
        float4 b = *(const float4*)&E[(size_t)row * NDIM + k8 + 4];
        v[0] = a.x; v[1] = a.y; v[2] = a.z; v[3] = a.w;
        v[4] = b.x; v[5] = b.y; v[6] = b.z; v[7] = b.w;
    } else {
#pragma unroll
        for (int i = 0; i < 8; i++) v[i] = 0.f;
    }
    __align__(16) __nv_bfloat16 hb[8];
#pragma unroll
    for (int i = 0; i < 8; i++) hb[i] = __float2bfloat16(v[i]);
    *(uint4*)&g_Ehi[(size_t)row * NDIM + k8] = *(uint4*)hb;
}

// ---------------- kernel 3: vectors + label scores + L1 zero (fused) --------
// Runs AFTER convert_e (reads g_Ehi for sy). One block per fact.
__global__ void build_vec_kernel(const int* __restrict__ facts,
                                 const int* __restrict__ arch,
                                 const float* __restrict__ ent_w,
                                 const float* __restrict__ rel_w) {
    int b = blockIdx.x, tid = threadIdx.x;
    __shared__ float hen[256], ten[256], ren[256], al[64], red[256];
    int h = facts[3 * b], t = facts[3 * b + 1], r = facts[3 * b + 2];
    hen[tid] = ent_w[h * NDIM + tid] * g_scale[tid]       + g_shift[tid];
    ten[tid] = ent_w[t * NDIM + tid] * g_scale[256 + tid] + g_shift[256 + tid];
    ren[tid] = rel_w[r * NDIM + tid] * g_scale[512 + tid] + g_shift[512 + tid];
    if (tid < 64) {
        int a = arch[tid];
        al[tid] = (a == 1) ? 1.f : ((a == 2) ? -1.f : 0.f);
    }
    __syncthreads();
    int k = tid >> 6, l = tid & 63;
    float hv = 0.f, tv = 0.f;
#pragma unroll
    for (int i = 0; i < 4; i++) {
        float rv = ren[i * 64 + l];
#pragma unroll
        for (int j = 0; j < 4; j++) {
            hv += al[i * 16 + j * 4 + k] * rv * ten[j * 64 + l];
            tv += al[i * 16 + k * 4 + j] * rv * hen[j * 64 + l];
        }
    }
    g_Vhi[b * NDIM + tid]         = __float2bfloat16(hv);
    g_Vhi[(BSZ + b) * NDIM + tid] = __float2bfloat16(tv);

    // label scores: sy_head = hv . Ehi[h],  sy_tail = tv . Ehi[t]
    float eh = __bfloat162float(g_Ehi[(size_t)h * NDIM + tid]);
    float et = __bfloat162float(g_Ehi[(size_t)t * NDIM + tid]);
    red[tid] = hv * eh; __syncthreads();
    for (int o = 128; o > 0; o >>= 1) {
        if (tid < o) red[tid] += red[tid + o];
        __syncthreads();
    }
    if (tid == 0) g_sy[b] = red[0];
    __syncthreads();
    red[tid] = tv * et; __syncthreads();
    for (int o = 128; o > 0; o >>= 1) {
        if (tid < o) red[tid] += red[tid + o];
        __syncthreads();
    }
    if (tid == 0) {
        g_sy[BSZ + b] = red[0];
        g_L1[b] = 0.f; g_L1[BSZ + b] = 0.f;
    }
}

// ---------------- kernel 4: bf16 HMMA GEMM + fused L1 epilogue --------------
// BM=128, BN=128. A tile (128x256 = 64KB) loaded ONCE; B double-buffered
// (2 x 16KB, BK=64). 8 warps (4m x 2n), warp tile 32x64.
// Epilogue: L1 += exp(s-16) (MUFU/FMA-poly interleave).
#define SMEM_A_BYTES   65536
#define SMEM_B_STAGE   16384
#define SMEM_TOTAL_GEMM (SMEM_A_BYTES + 2 * SMEM_B_STAGE)   // 96KB
#define SHIFT16_LOG2 23.083120654223414f   // 16 * log2(e)
#define LOG2E        1.44269504088896f

__global__ __launch_bounds__(256, 2) void gemm_kernel() {
    extern __shared__ __align__(128) char smem[];
    uint32_t sbase = smem_to_u32(smem);
    int tid = threadIdx.x, lane = tid & 31, w = tid >> 5;
    int n0g = blockIdx.x * 128, m0 = blockIdx.y * 128;
    int wm = w >> 1, wn = w & 1;

    float acc[2][8][4];
#pragma unroll
    for (int i = 0; i < 2; i++)
#pragma unroll
        for (int j = 0; j < 8; j++)
#pragma unroll
            for (int q = 0; q < 4; q++) acc[i][j][q] = 0.f;

    // ---- prologue: full A tile (128 rows x 32 16B-chunks), group 0 with B0
    {
#pragma unroll
        for (int i = 0; i < 16; i++) {
            int c = tid + i * 256;            // 0..4095
            int row = c >> 5, pos = c & 31;
            uint32_t off = (uint32_t)(row * 512 + ((pos ^ (row & 7)) << 4));
            cp16(sbase + off, g_Vhi + (size_t)(m0 + row) * NDIM + pos * 8);
        }
    }
    int b_row[4], b_pos[4]; uint32_t b_soff[4];
#pragma unroll
    for (int i = 0; i < 4; i++) {
        int c = tid + i * 256;                // 0..1023
        b_row[i] = c >> 3;
        b_pos[i] = c & 7;
        b_soff[i] = (uint32_t)(b_row[i] * 128 + ((b_pos[i] ^ (b_row[i] & 7)) << 4));
    }
    auto load_B = [&](int kt, int s) {
        int kk = kt * 64;
        uint32_t sB = sbase + SMEM_A_BYTES + (uint32_t)s * SMEM_B_STAGE;
#pragma unroll
        for (int i = 0; i < 4; i++)
            cp16(sB + b_soff[i], g_Ehi + (size_t)(n0g + b_row[i]) * NDIM + kk + b_pos[i] * 8);
        cp_commit();
    };
    load_B(0, 0);   // group 0 (A + B0)
    load_B(1, 1);   // group 1

    for (int kt = 0; kt < 4; kt++) {
        int s = kt & 1;
        if (kt < 3) cp_wait<1>(); else cp_wait<0>();
        __syncthreads();

        uint32_t sB = sbase + SMEM_A_BYTES + (uint32_t)s * SMEM_B_STAGE;
#pragma unroll
        for (int ks = 0; ks < 4; ks++) {
            uint32_t br[4][4];
#pragma unroll
            for (int nb = 0; nb < 4; nb++) {
                int n = wn * 64 + nb * 16 + (lane & 7) + ((lane >> 4) & 1) * 8;
                int chunk = ks * 2 + ((lane >> 3) & 1);
                ldsm_x4(br[nb], sB + (uint32_t)(n * 128 + ((chunk ^ (n & 7)) << 4)));
            }
            uint32_t ar[2][4];
#pragma unroll
            for (int mf = 0; mf < 2; mf++) {
                int row = wm * 32 + mf * 16 + (lane & 15);
                int chunk = kt * 8 + ks * 2 + (lane >> 4);       // full-K A tile
                ldsm_x4(ar[mf], sbase + (uint32_t)(row * 512 + ((chunk ^ (row & 7)) << 4)));
            }
#pragma unroll
            for (int mf = 0; mf < 2; mf++)
#pragma unroll
                for (int nb = 0; nb < 4; nb++) {
                    mma16816(acc[mf][nb * 2],     ar[mf], br[nb][0], br[nb][1]);
                    mma16816(acc[mf][nb * 2 + 1], ar[mf], br[nb][2], br[nb][3]);
                }
        }
        __syncthreads();
        if (kt < 2) load_B(kt + 2, s);   // refill the stage just consumed
    }

    // ---- fused epilogue: per-row L1; MUFU + FMA-poly exp interleave ----
#pragma unroll
    for (int mf = 0; mf < 2; mf++) {
#pragma unroll
        for (int half = 0; half < 2; half++) {
            float a1 = 0.f;
#pragma unroll
            for (int nf = 0; nf < 8; nf++) {
                float s0 = acc[mf][nf][half * 2];
                float s1 = acc[mf][nf][half * 2 + 1];
                a1 += exp2f(fmaf(s0, LOG2E, -SHIFT16_LOG2));   // MUFU pipe
                a1 += fexp2(fmaf(s1, LOG2E, -SHIFT16_LOG2));   // FMA/ALU pipes
            }
            a1 += __shfl_xor_sync(0xffffffffu, a1, 1);
            a1 += __shfl_xor_sync(0xffffffffu, a1, 2);
            if ((lane & 3) == 0) {
                int row = m0 + wm * 32 + mf * 16 + half * 8 + (lane >> 2);
                atomicAdd(&g_L1[row], a1);
            }
        }
    }
}

// ---------------- kernel 5: finalize loss from (L1, sy) ---------------------
__global__ void finalize_kernel(float* out) {
    int tid = threadIdx.x;
    float padL1 = (float)N_PAD_COLS * exp2f(-SHIFT16_LOG2);  // 48 cols with s=0
    double acc = 0.0;
    for (int r = tid; r < M_ROWS; r += 256) {
        float L1 = g_L1[r] - padL1;
        float lse = 16.f + logf(L1);
        float sum_lm = -1.f;                 // -(S1=1)
        float dy = g_sy[r] - lse;
        float logp = fmaxf(dy, -100.f);
        float py = __expf(dy);
        float lm_y = fmaxf(log1pf(-py), -100.f);
        acc += (double)sum_lm + (double)logp - (double)lm_y;
    }
    __shared__ double rd[256];
    rd[tid] = acc; __syncthreads();
    for (int o = 128; o > 0; o >>= 1) {
        if (tid < o) rd[tid] += rd[tid + o];
        __syncthreads();
    }
    if (tid == 0)
        out[0] = (float)(-rd[0] * (1.0 / ((double)BSZ * (double)N_ENT)));
}

// ---------------- launch ----------------------------------------------------
extern "C" void kernel_launch(void* const* d_in, const int* in_sizes, int n_in,
                              void* d_out, int out_size) {
    const int*   facts = (const int*)d_in[0];
    const int*   arch  = (const int*)d_in[1];
    const float* ent_w = (const float*)d_in[2];
    const float* rel_w = (const float*)d_in[3];
    const float* bg_e  = (const float*)d_in[4];
    const float* bb_e  = (const float*)d_in[5];
    const float* bg_r  = (const float*)d_in[6];
    const float* bb_r  = (const float*)d_in[7];
    float* out = (float*)d_out;

    cudaFuncSetAttribute(gemm_kernel, cudaFuncAttributeMaxDynamicSharedMemorySize,
                         SMEM_TOTAL_GEMM);

    bn_stats_kernel<<<dim3(256, 3), 256>>>(facts, ent_w, rel_w, bg_e, bb_e, bg_r, bb_r);
    convert_e_kernel<<<6256, 256>>>(ent_w);
    build_vec_kernel<<<BSZ, 256>>>(facts, arch, ent_w, rel_w);   // + sy + L1 zero
    gemm_kernel<<<dim3(NPAD / 128, M_ROWS / 128), 256, SMEM_TOTAL_GEMM>>>();
    finalize_kernel<<<1, 256>>>(out);
}

// round 13
// speedup vs baseline: 10.0435x; 1.0911x over previous
#include <cuda_runtime.h>
#include <cuda_bf16.h>
#include <cuda_fp16.h>
#include <math.h>
#include <stdint.h>

#define N_ENT  50000
#define NDIM   256
#define BSZ    1024
#define M_ROWS 2048
#define NPAD   50048          // 391 * 128
#define N_PAD_COLS (NPAD - N_ENT)   // 48, deterministic s=0 columns
#define CONV_BLOCKS 6256

// ---------------- device scratch ----------------
__device__ float          g_scale[768];
__device__ float          g_shift[768];
__device__ __nv_bfloat16  g_Vhi[M_ROWS * NDIM];
__device__ __nv_bfloat16  g_Ehi[(size_t)NPAD * NDIM];
__device__ float          g_L1[M_ROWS];
__device__ float          g_sy[M_ROWS];

// ---------------- PTX helpers (sm_103-base-safe) ----------------
__device__ __forceinline__ uint32_t smem_to_u32(const void* p) {
    uint32_t a;
    asm("{ .reg .u64 t; cvta.to.shared.u64 t, %1; cvt.u32.u64 %0, t; }" : "=r"(a) : "l"(p));
    return a;
}
__device__ __forceinline__ void cp16(uint32_t s, const void* g) {
    asm volatile("cp.async.cg.shared.global [%0], [%1], 16;" :: "r"(s), "l"(g) : "memory");
}
__device__ __forceinline__ void cp_commit() {
    asm volatile("cp.async.commit_group;" ::: "memory");
}
template <int N>
__device__ __forceinline__ void cp_wait() {
    asm volatile("cp.async.wait_group %0;" :: "n"(N) : "memory");
}
__device__ __forceinline__ void ldsm_x4(uint32_t* r, uint32_t a) {
    asm volatile("ldmatrix.sync.aligned.m8n8.x4.shared.b16 {%0,%1,%2,%3}, [%4];"
                 : "=r"(r[0]), "=r"(r[1]), "=r"(r[2]), "=r"(r[3]) : "r"(a));
}
__device__ __forceinline__ void mma16816(float* c, const uint32_t* a, uint32_t b0, uint32_t b1) {
    asm volatile("mma.sync.aligned.m16n8k16.row.col.f32.bf16.bf16.f32 "
                 "{%0,%1,%2,%3}, {%4,%5,%6,%7}, {%8,%9}, {%0,%1,%2,%3};"
                 : "+f"(c[0]), "+f"(c[1]), "+f"(c[2]), "+f"(c[3])
                 : "r"(a[0]), "r"(a[1]), "r"(a[2]), "r"(a[3]), "r"(b0), "r"(b1));
}

// ---------------- kernel 1: fused ent_w->bf16 convert + BN statistics -------
// blocks [0, CONV_BLOCKS): convert 8 rows' worth of 8-float chunks each.
// blocks [CONV_BLOCKS, CONV_BLOCKS+768): BN stats (s = sub/256, d = sub%256).
__global__ void prep_kernel(const int* __restrict__ facts,
                            const float* __restrict__ ent_w,
                            const float* __restrict__ rel_w,
                            const float* __restrict__ bg_e,
                            const float* __restrict__ bb_e,
                            const float* __restrict__ bg_r,
                            const float* __restrict__ bb_r) {
    int tid = threadIdx.x;
    if (blockIdx.x < CONV_BLOCKS) {
        int t = blockIdx.x * 256 + tid;
        int row = t >> 5;
        int k8  = (t & 31) * 8;
        float v[8];
        if (row < N_ENT) {
            float4 a = *(const float4*)&ent_w[(size_t)row * NDIM + k8];
            float4 b = *(const float4*)&ent_w[(size_t)row * NDIM + k8 + 4];
            v[0] = a.x; v[1] = a.y; v[2] = a.z; v[3] = a.w;
            v[4] = b.x; v[5] = b.y; v[6] = b.z; v[7] = b.w;
        } else {
#pragma unroll
            for (int i = 0; i < 8; i++) v[i] = 0.f;
        }
        __align__(16) __nv_bfloat16 hb[8];
#pragma unroll
        for (int i = 0; i < 8; i++) hb[i] = __float2bfloat16(v[i]);
        *(uint4*)&g_Ehi[(size_t)row * NDIM + k8] = *(uint4*)hb;
        return;
    }
    int sub = blockIdx.x - CONV_BLOCKS;      // 0..767
    int s = sub >> 8, d = sub & 255;
    const float* W = (s == 2) ? rel_w : ent_w;
    float sum = 0.f, sq = 0.f;
    for (int b = tid; b < BSZ; b += 256) {
        int idx = facts[b * 3 + s];
        float x = W[idx * NDIM + d];
        sum += x; sq += x * x;
    }
    __shared__ float s1[256], s2[256];
    s1[tid] = sum; s2[tid] = sq; __syncthreads();
    for (int o = 128; o > 0; o >>= 1) {
        if (tid < o) { s1[tid] += s1[tid + o]; s2[tid] += s2[tid + o]; }
        __syncthreads();
    }
    if (tid == 0) {
        float mean = s1[0] * (1.f / BSZ);
        float var  = s2[0] * (1.f / BSZ) - mean * mean;
        float gamma = (s == 2) ? bg_r[d] : bg_e[d];
        float beta  = (s == 2) ? bb_r[d] : bb_e[d];
        float sc = gamma * rsqrtf(var + 1e-5f);
        g_scale[s * 256 + d] = sc;
        g_shift[s * 256 + d] = beta - mean * sc;
    }
}

// ---------------- kernel 2: vectors + label scores + L1 zero (fused) --------
__global__ void build_vec_kernel(const int* __restrict__ facts,
                                 const int* __restrict__ arch,
                                 const float* __restrict__ ent_w,
                                 const float* __restrict__ rel_w) {
    int b = blockIdx.x, tid = threadIdx.x;
    __shared__ float hen[256], ten[256], ren[256], al[64], red[256];
    int h = facts[3 * b], t = facts[3 * b + 1], r = facts[3 * b + 2];
    hen[tid] = ent_w[h * NDIM + tid] * g_scale[tid]       + g_shift[tid];
    ten[tid] = ent_w[t * NDIM + tid] * g_scale[256 + tid] + g_shift[256 + tid];
    ren[tid] = rel_w[r * NDIM + tid] * g_scale[512 + tid] + g_shift[512 + tid];
    if (tid < 64) {
        int a = arch[tid];
        al[tid] = (a == 1) ? 1.f : ((a == 2) ? -1.f : 0.f);
    }
    __syncthreads();
    int k = tid >> 6, l = tid & 63;
    float hv = 0.f, tv = 0.f;
#pragma unroll
    for (int i = 0; i < 4; i++) {
        float rv = ren[i * 64 + l];
#pragma unroll
        for (int j = 0; j < 4; j++) {
            hv += al[i * 16 + j * 4 + k] * rv * ten[j * 64 + l];
            tv += al[i * 16 + k * 4 + j] * rv * hen[j * 64 + l];
        }
    }
    g_Vhi[b * NDIM + tid]         = __float2bfloat16(hv);
    g_Vhi[(BSZ + b) * NDIM + tid] = __float2bfloat16(tv);

    float eh = __bfloat162float(g_Ehi[(size_t)h * NDIM + tid]);
    float et = __bfloat162float(g_Ehi[(size_t)t * NDIM + tid]);
    red[tid] = hv * eh; __syncthreads();
    for (int o = 128; o > 0; o >>= 1) {
        if (tid < o) red[tid] += red[tid + o];
        __syncthreads();
    }
    if (tid == 0) g_sy[b] = red[0];
    __syncthreads();
    red[tid] = tv * et; __syncthreads();
    for (int o = 128; o > 0; o >>= 1) {
        if (tid < o) red[tid] += red[tid + o];
        __syncthreads();
    }
    if (tid == 0) {
        g_sy[BSZ + b] = red[0];
        g_L1[b] = 0.f; g_L1[BSZ + b] = 0.f;
    }
}

// ---------------- kernel 3: bf16 HMMA GEMM + fused L1 epilogue --------------
// BM=128, BN=128. A tile (128x256 = 64KB) loaded ONCE; B double-buffered
// (2 x 16KB, BK=64). 8 warps (4m x 2n), warp tile 32x64.
// Epilogue: L1 += exp(s-16), all-MUFU (minimal instruction count).
#define SMEM_A_BYTES   65536
#define SMEM_B_STAGE   16384
#define SMEM_TOTAL_GEMM (SMEM_A_BYTES + 2 * SMEM_B_STAGE)   // 96KB
#define SHIFT16_LOG2 23.083120654223414f   // 16 * log2(e)
#define LOG2E        1.44269504088896f

__global__ __launch_bounds__(256, 2) void gemm_kernel() {
    extern __shared__ __align__(128) char smem[];
    uint32_t sbase = smem_to_u32(smem);
    int tid = threadIdx.x, lane = tid & 31, w = tid >> 5;
    int n0g = blockIdx.x * 128, m0 = blockIdx.y * 128;
    int wm = w >> 1, wn = w & 1;

    float acc[2][8][4];
#pragma unroll
    for (int i = 0; i < 2; i++)
#pragma unroll
        for (int j = 0; j < 8; j++)
#pragma unroll
            for (int q = 0; q < 4; q++) acc[i][j][q] = 0.f;

    // ---- prologue: full A tile (128 rows x 32 16B-chunks), group 0 with B0
    {
#pragma unroll
        for (int i = 0; i < 16; i++) {
            int c = tid + i * 256;            // 0..4095
            int row = c >> 5, pos = c & 31;
            uint32_t off = (uint32_t)(row * 512 + ((pos ^ (row & 7)) << 4));
            cp16(sbase + off, g_Vhi + (size_t)(m0 + row) * NDIM + pos * 8);
        }
    }
    int b_row[4], b_pos[4]; uint32_t b_soff[4];
#pragma unroll
    for (int i = 0; i < 4; i++) {
        int c = tid + i * 256;                // 0..1023
        b_row[i] = c >> 3;
        b_pos[i] = c & 7;
        b_soff[i] = (uint32_t)(b_row[i] * 128 + ((b_pos[i] ^ (b_row[i] & 7)) << 4));
    }
    auto load_B = [&](int kt, int s) {
        int kk = kt * 64;
        uint32_t sB = sbase + SMEM_A_BYTES + (uint32_t)s * SMEM_B_STAGE;
#pragma unroll
        for (int i = 0; i < 4; i++)
            cp16(sB + b_soff[i], g_Ehi + (size_t)(n0g + b_row[i]) * NDIM + kk + b_pos[i] * 8);
        cp_commit();
    };
    load_B(0, 0);
    load_B(1, 1);

    for (int kt = 0; kt < 4; kt++) {
        int s = kt & 1;
        if (kt < 3) cp_wait<1>(); else cp_wait<0>();
        __syncthreads();

        uint32_t sB = sbase + SMEM_A_BYTES + (uint32_t)s * SMEM_B_STAGE;
#pragma unroll
        for (int ks = 0; ks < 4; ks++) {
            uint32_t br[4][4];
#pragma unroll
            for (int nb = 0; nb < 4; nb++) {
                int n = wn * 64 + nb * 16 + (lane & 7) + ((lane >> 4) & 1) * 8;
                int chunk = ks * 2 + ((lane >> 3) & 1);
                ldsm_x4(br[nb], sB + (uint32_t)(n * 128 + ((chunk ^ (n & 7)) << 4)));
            }
            uint32_t ar[2][4];
#pragma unroll
            for (int mf = 0; mf < 2; mf++) {
                int row = wm * 32 + mf * 16 + (lane & 15);
                int chunk = kt * 8 + ks * 2 + (lane >> 4);
                ldsm_x4(ar[mf], sbase + (uint32_t)(row * 512 + ((chunk ^ (row & 7)) << 4)));
            }
#pragma unroll
            for (int mf = 0; mf < 2; mf++)
#pragma unroll
                for (int nb = 0; nb < 4; nb++) {
                    mma16816(acc[mf][nb * 2],     ar[mf], br[nb][0], br[nb][1]);
                    mma16816(acc[mf][nb * 2 + 1], ar[mf], br[nb][2], br[nb][3]);
                }
        }
        __syncthreads();
        if (kt < 2) load_B(kt + 2, s);
    }

    // ---- fused epilogue: per-row L1, all-MUFU exp ----
#pragma unroll
    for (int mf = 0; mf < 2; mf++) {
#pragma unroll
        for (int half = 0; half < 2; half++) {
            float a1 = 0.f;
#pragma unroll
            for (int nf = 0; nf < 8; nf++) {
                a1 += exp2f(fmaf(acc[mf][nf][half * 2],     LOG2E, -SHIFT16_LOG2));
                a1 += exp2f(fmaf(acc[mf][nf][half * 2 + 1], LOG2E, -SHIFT16_LOG2));
            }
            a1 += __shfl_xor_sync(0xffffffffu, a1, 1);
            a1 += __shfl_xor_sync(0xffffffffu, a1, 2);
            if ((lane & 3) == 0) {
                int row = m0 + wm * 32 + mf * 16 + half * 8 + (lane >> 2);
                atomicAdd(&g_L1[row], a1);
            }
        }
    }
}

// ---------------- kernel 4: finalize loss from (L1, sy) ---------------------
__global__ void finalize_kernel(float* out) {
    int tid = threadIdx.x;
    float padL1 = (float)N_PAD_COLS * exp2f(-SHIFT16_LOG2);
    double acc = 0.0;
    for (int r = tid; r < M_ROWS; r += 256) {
        float L1 = g_L1[r] - padL1;
        float lse = 16.f + logf(L1);
        float sum_lm = -1.f;
        float dy = g_sy[r] - lse;
        float logp = fmaxf(dy, -100.f);
        float py = __expf(dy);
        float lm_y = fmaxf(log1pf(-py), -100.f);
        acc += (double)sum_lm + (double)logp - (double)lm_y;
    }
    __shared__ double rd[256];
    rd[tid] = acc; __syncthreads();
    for (int o = 128; o > 0; o >>= 1) {
        if (tid < o) rd[tid] += rd[tid + o];
        __syncthreads();
    }
    if (tid == 0)
        out[0] = (float)(-rd[0] * (1.0 / ((double)BSZ * (double)N_ENT)));
}

// ---------------- launch ----------------------------------------------------
extern "C" void kernel_launch(void* const* d_in, const int* in_sizes, int n_in,
                              void* d_out, int out_size) {
    const int*   facts = (const int*)d_in[0];
    const int*   arch  = (const int*)d_in[1];
    const float* ent_w = (const float*)d_in[2];
    const float* rel_w = (const float*)d_in[3];
    const float* bg_e  = (const float*)d_in[4];
    const float* bb_e  = (const float*)d_in[5];
    const float* bg_r  = (const float*)d_in[6];
    const float* bb_r  = (const float*)d_in[7];
    float* out = (float*)d_out;

    cudaFuncSetAttribute(gemm_kernel, cudaFuncAttributeMaxDynamicSharedMemorySize,
                         SMEM_TOTAL_GEMM);

    prep_kernel<<<CONV_BLOCKS + 768, 256>>>(facts, ent_w, rel_w, bg_e, bb_e, bg_r, bb_r);
    build_vec_kernel<<<BSZ, 256>>>(facts, arch, ent_w, rel_w);
    gemm_kernel<<<dim3(NPAD / 128, M_ROWS / 128), 256, SMEM_TOTAL_GEMM>>>();
    finalize_kernel<<<1, 256>>>(out);
}

// round 14
// speedup vs baseline: 10.2002x; 1.0156x over previous
#include <cuda_runtime.h>
#include <cuda_bf16.h>
#include <cuda_fp16.h>
#include <math.h>
#include <stdint.h>

#define N_ENT  50000
#define NDIM   256
#define BSZ    1024
#define M_ROWS 2048
#define NPAD   50048          // 391 * 128
#define N_PAD_COLS (NPAD - N_ENT)   // 48, deterministic s=0 columns
#define CONV_BLOCKS 6256

// ---------------- device scratch ----------------
__device__ float          g_scale[768];
__device__ float          g_shift[768];
__device__ __nv_bfloat16  g_Vhi[M_ROWS * NDIM];
__device__ __nv_bfloat16  g_Ehi[(size_t)NPAD * NDIM];
__device__ float          g_L1[M_ROWS];
__device__ float          g_sy[M_ROWS];

// ---------------- PTX helpers (sm_103-base-safe) ----------------
__device__ __forceinline__ uint32_t smem_to_u32(const void* p) {
    uint32_t a;
    asm("{ .reg .u64 t; cvta.to.shared.u64 t, %1; cvt.u32.u64 %0, t; }" : "=r"(a) : "l"(p));
    return a;
}
__device__ __forceinline__ void cp16(uint32_t s, const void* g) {
    asm volatile("cp.async.cg.shared.global [%0], [%1], 16;" :: "r"(s), "l"(g) : "memory");
}
__device__ __forceinline__ void cp_commit() {
    asm volatile("cp.async.commit_group;" ::: "memory");
}
template <int N>
__device__ __forceinline__ void cp_wait() {
    asm volatile("cp.async.wait_group %0;" :: "n"(N) : "memory");
}
__device__ __forceinline__ void ldsm_x4(uint32_t* r, uint32_t a) {
    asm volatile("ldmatrix.sync.aligned.m8n8.x4.shared.b16 {%0,%1,%2,%3}, [%4];"
                 : "=r"(r[0]), "=r"(r[1]), "=r"(r[2]), "=r"(r[3]) : "r"(a));
}
__device__ __forceinline__ void mma16816(float* c, const uint32_t* a, uint32_t b0, uint32_t b1) {
    asm volatile("mma.sync.aligned.m16n8k16.row.col.f32.bf16.bf16.f32 "
                 "{%0,%1,%2,%3}, {%4,%5,%6,%7}, {%8,%9}, {%0,%1,%2,%3};"
                 : "+f"(c[0]), "+f"(c[1]), "+f"(c[2]), "+f"(c[3])
                 : "r"(a[0]), "r"(a[1]), "r"(a[2]), "r"(a[3]), "r"(b0), "r"(b1));
}

// ---------------- kernel 1: fused ent_w->bf16 convert + BN statistics -------
__global__ void prep_kernel(const int* __restrict__ facts,
                            const float* __restrict__ ent_w,
                            const float* __restrict__ rel_w,
                            const float* __restrict__ bg_e,
                            const float* __restrict__ bb_e,
                            const float* __restrict__ bg_r,
                            const float* __restrict__ bb_r) {
    int tid = threadIdx.x;
    if (blockIdx.x < CONV_BLOCKS) {
        int t = blockIdx.x * 256 + tid;
        int row = t >> 5;
        int k8  = (t & 31) * 8;
        float v[8];
        if (row < N_ENT) {
            float4 a = *(const float4*)&ent_w[(size_t)row * NDIM + k8];
            float4 b = *(const float4*)&ent_w[(size_t)row * NDIM + k8 + 4];
            v[0] = a.x; v[1] = a.y; v[2] = a.z; v[3] = a.w;
            v[4] = b.x; v[5] = b.y; v[6] = b.z; v[7] = b.w;
        } else {
#pragma unroll
            for (int i = 0; i < 8; i++) v[i] = 0.f;
        }
        __align__(16) __nv_bfloat16 hb[8];
#pragma unroll
        for (int i = 0; i < 8; i++) hb[i] = __float2bfloat16(v[i]);
        *(uint4*)&g_Ehi[(size_t)row * NDIM + k8] = *(uint4*)hb;
        return;
    }
    int sub = blockIdx.x - CONV_BLOCKS;      // 0..767
    int s = sub >> 8, d = sub & 255;
    const float* W = (s == 2) ? rel_w : ent_w;
    float sum = 0.f, sq = 0.f;
    for (int b = tid; b < BSZ; b += 256) {
        int idx = facts[b * 3 + s];
        float x = W[idx * NDIM + d];
        sum += x; sq += x * x;
    }
    __shared__ float s1[256], s2[256];
    s1[tid] = sum; s2[tid] = sq; __syncthreads();
    for (int o = 128; o > 0; o >>= 1) {
        if (tid < o) { s1[tid] += s1[tid + o]; s2[tid] += s2[tid + o]; }
        __syncthreads();
    }
    if (tid == 0) {
        float mean = s1[0] * (1.f / BSZ);
        float var  = s2[0] * (1.f / BSZ) - mean * mean;
        float gamma = (s == 2) ? bg_r[d] : bg_e[d];
        float beta  = (s == 2) ? bb_r[d] : bb_e[d];
        float sc = gamma * rsqrtf(var + 1e-5f);
        g_scale[s * 256 + d] = sc;
        g_shift[s * 256 + d] = beta - mean * sc;
    }
}

// ---------------- kernel 2: vectors + label scores + L1 zero (fused) --------
__global__ void build_vec_kernel(const int* __restrict__ facts,
                                 const int* __restrict__ arch,
                                 const float* __restrict__ ent_w,
                                 const float* __restrict__ rel_w) {
    int b = blockIdx.x, tid = threadIdx.x;
    __shared__ float hen[256], ten[256], ren[256], al[64], red[256];
    int h = facts[3 * b], t = facts[3 * b + 1], r = facts[3 * b + 2];
    hen[tid] = ent_w[h * NDIM + tid] * g_scale[tid]       + g_shift[tid];
    ten[tid] = ent_w[t * NDIM + tid] * g_scale[256 + tid] + g_shift[256 + tid];
    ren[tid] = rel_w[r * NDIM + tid] * g_scale[512 + tid] + g_shift[512 + tid];
    if (tid < 64) {
        int a = arch[tid];
        al[tid] = (a == 1) ? 1.f : ((a == 2) ? -1.f : 0.f);
    }
    __syncthreads();
    int k = tid >> 6, l = tid & 63;
    float hv = 0.f, tv = 0.f;
#pragma unroll
    for (int i = 0; i < 4; i++) {
        float rv = ren[i * 64 + l];
#pragma unroll
        for (int j = 0; j < 4; j++) {
            hv += al[i * 16 + j * 4 + k] * rv * ten[j * 64 + l];
            tv += al[i * 16 + k * 4 + j] * rv * hen[j * 64 + l];
        }
    }
    g_Vhi[b * NDIM + tid]         = __float2bfloat16(hv);
    g_Vhi[(BSZ + b) * NDIM + tid] = __float2bfloat16(tv);

    float eh = __bfloat162float(g_Ehi[(size_t)h * NDIM + tid]);
    float et = __bfloat162float(g_Ehi[(size_t)t * NDIM + tid]);
    red[tid] = hv * eh; __syncthreads();
    for (int o = 128; o > 0; o >>= 1) {
        if (tid < o) red[tid] += red[tid + o];
        __syncthreads();
    }
    if (tid == 0) g_sy[b] = red[0];
    __syncthreads();
    red[tid] = tv * et; __syncthreads();
    for (int o = 128; o > 0; o >>= 1) {
        if (tid < o) red[tid] += red[tid + o];
        __syncthreads();
    }
    if (tid == 0) {
        g_sy[BSZ + b] = red[0];
        g_L1[b] = 0.f; g_L1[BSZ + b] = 0.f;
    }
}

// ---------------- kernel 3: bf16 HMMA GEMM + fused L1 epilogue --------------
// BM=128, BN=128. A tile (128x256 = 64KB) loaded ONCE; B triple-buffered
// (3 x 16KB, BK=64) -> 112KB/CTA, 2 CTAs/SM. 8 warps (4m x 2n), warp 32x64.
#define SMEM_A_BYTES   65536
#define SMEM_B_STAGE   16384
#define SMEM_TOTAL_GEMM (SMEM_A_BYTES + 3 * SMEM_B_STAGE)   // 112KB
#define SHIFT16_LOG2 23.083120654223414f   // 16 * log2(e)
#define LOG2E        1.44269504088896f

__global__ __launch_bounds__(256, 2) void gemm_kernel() {
    extern __shared__ __align__(128) char smem[];
    uint32_t sbase = smem_to_u32(smem);
    int tid = threadIdx.x, lane = tid & 31, w = tid >> 5;
    int n0g = blockIdx.x * 128, m0 = blockIdx.y * 128;
    int wm = w >> 1, wn = w & 1;

    float acc[2][8][4];
#pragma unroll
    for (int i = 0; i < 2; i++)
#pragma unroll
        for (int j = 0; j < 8; j++)
#pragma unroll
            for (int q = 0; q < 4; q++) acc[i][j][q] = 0.f;

    // ---- prologue: full A tile (128 rows x 32 16B-chunks) + B stages 0..2
    {
#pragma unroll
        for (int i = 0; i < 16; i++) {
            int c = tid + i * 256;            // 0..4095
            int row = c >> 5, pos = c & 31;
            uint32_t off = (uint32_t)(row * 512 + ((pos ^ (row & 7)) << 4));
            cp16(sbase + off, g_Vhi + (size_t)(m0 + row) * NDIM + pos * 8);
        }
    }
    int b_row[4], b_pos[4]; uint32_t b_soff[4];
#pragma unroll
    for (int i = 0; i < 4; i++) {
        int c = tid + i * 256;                // 0..1023
        b_row[i] = c >> 3;
        b_pos[i] = c & 7;
        b_soff[i] = (uint32_t)(b_row[i] * 128 + ((b_pos[i] ^ (b_row[i] & 7)) << 4));
    }
    auto load_B = [&](int kt, int s) {
        int kk = kt * 64;
        uint32_t sB = sbase + SMEM_A_BYTES + (uint32_t)s * SMEM_B_STAGE;
#pragma unroll
        for (int i = 0; i < 4; i++)
            cp16(sB + b_soff[i], g_Ehi + (size_t)(n0g + b_row[i]) * NDIM + kk + b_pos[i] * 8);
        cp_commit();
    };
    load_B(0, 0);   // group 0 (with A)
    load_B(1, 1);   // group 1
    load_B(2, 2);   // group 2

    for (int kt = 0; kt < 4; kt++) {
        int s = kt % 3;
        // ensure tile kt's group has landed
        if (kt <= 1) cp_wait<2>();
        else if (kt == 2) cp_wait<1>();
        else cp_wait<0>();
        __syncthreads();

        uint32_t sB = sbase + SMEM_A_BYTES + (uint32_t)s * SMEM_B_STAGE;
#pragma unroll
        for (int ks = 0; ks < 4; ks++) {
            uint32_t br[4][4];
#pragma unroll
            for (int nb = 0; nb < 4; nb++) {
                int n = wn * 64 + nb * 16 + (lane & 7) + ((lane >> 4) & 1) * 8;
                int chunk = ks * 2 + ((lane >> 3) & 1);
                ldsm_x4(br[nb], sB + (uint32_t)(n * 128 + ((chunk ^ (n & 7)) << 4)));
            }
            uint32_t ar[2][4];
#pragma unroll
            for (int mf = 0; mf < 2; mf++) {
                int row = wm * 32 + mf * 16 + (lane & 15);
                int chunk = kt * 8 + ks * 2 + (lane >> 4);
                ldsm_x4(ar[mf], sbase + (uint32_t)(row * 512 + ((chunk ^ (row & 7)) << 4)));
            }
#pragma unroll
            for (int mf = 0; mf < 2; mf++)
#pragma unroll
                for (int nb = 0; nb < 4; nb++) {
                    mma16816(acc[mf][nb * 2],     ar[mf], br[nb][0], br[nb][1]);
                    mma16816(acc[mf][nb * 2 + 1], ar[mf], br[nb][2], br[nb][3]);
                }
        }
        __syncthreads();
        if (kt == 0) load_B(3, 0);   // refill stage 0 with the last tile
    }

    // ---- fused epilogue: per-row L1, all-MUFU exp ----
#pragma unroll
    for (int mf = 0; mf < 2; mf++) {
#pragma unroll
        for (int half = 0; half < 2; half++) {
            float a1 = 0.f;
#pragma unroll
            for (int nf = 0; nf < 8; nf++) {
                a1 += exp2f(fmaf(acc[mf][nf][half * 2],     LOG2E, -SHIFT16_LOG2));
                a1 += exp2f(fmaf(acc[mf][nf][half * 2 + 1], LOG2E, -SHIFT16_LOG2));
            }
            a1 += __shfl_xor_sync(0xffffffffu, a1, 1);
            a1 += __shfl_xor_sync(0xffffffffu, a1, 2);
            if ((lane & 3) == 0) {
                int row = m0 + wm * 32 + mf * 16 + half * 8 + (lane >> 2);
                atomicAdd(&g_L1[row], a1);
            }
        }
    }
}

// ---------------- kernel 4: finalize (1024 threads, 2 rows each) ------------
__global__ void finalize_kernel(float* out) {
    int tid = threadIdx.x;
    float padL1 = (float)N_PAD_COLS * exp2f(-SHIFT16_LOG2);
    float accf = 0.f;
    double acc = 0.0;
#pragma unroll
    for (int i = 0; i < 2; i++) {
        int r = tid + i * 1024;
        float L1 = g_L1[r] - padL1;
        float lse = 16.f + logf(L1);
        float dy = g_sy[r] - lse;
        float logp = fmaxf(dy, -100.f);
        float py = __expf(dy);
        float lm_y = fmaxf(log1pf(-py), -100.f);
        acc += (double)(-1.f) + (double)logp - (double)lm_y;
    }
    (void)accf;
    __shared__ double rd[1024];
    rd[tid] = acc; __syncthreads();
    for (int o = 512; o > 0; o >>= 1) {
        if (tid < o) rd[tid] += rd[tid + o];
        __syncthreads();
    }
    if (tid == 0)
        out[0] = (float)(-rd[0] * (1.0 / ((double)BSZ * (double)N_ENT)));
}

// ---------------- launch ----------------------------------------------------
extern "C" void kernel_launch(void* const* d_in, const int* in_sizes, int n_in,
                              void* d_out, int out_size) {
    const int*   facts = (const int*)d_in[0];
    const int*   arch  = (const int*)d_in[1];
    const float* ent_w = (const float*)d_in[2];
    const float* rel_w = (const float*)d_in[3];
    const float* bg_e  = (const float*)d_in[4];
    const float* bb_e  = (const float*)d_in[5];
    const float* bg_r  = (const float*)d_in[6];
    const float* bb_r  = (const float*)d_in[7];
    float* out = (float*)d_out;

    cudaFuncSetAttribute(gemm_kernel, cudaFuncAttributeMaxDynamicSharedMemorySize,
                         SMEM_TOTAL_GEMM);

    prep_kernel<<<CONV_BLOCKS + 768, 256>>>(facts, ent_w, rel_w, bg_e, bb_e, bg_r, bb_r);
    build_vec_kernel<<<BSZ, 256>>>(facts, arch, ent_w, rel_w);
    gemm_kernel<<<dim3(NPAD / 128, M_ROWS / 128), 256, SMEM_TOTAL_GEMM>>>();
    finalize_kernel<<<1, 1024>>>(out);
}